// round 11
// baseline (speedup 1.0000x reference)
#include <cuda_runtime.h>
#include <cuda_bf16.h>
#include <cstdint>

// ---------------------------------------------------------------------------
// Quaternion Hamilton-product tables
// ---------------------------------------------------------------------------
__constant__ int   c_cmp[16] = {0,1,2,3,  1,0,3,2,  2,3,0,1,  3,2,1,0};
__constant__ float c_sgn[16] = {1.f,-1.f,-1.f,-1.f,
                                1.f, 1.f, 1.f,-1.f,
                                1.f,-1.f, 1.f, 1.f,
                                1.f, 1.f,-1.f, 1.f};

// ---------------------------------------------------------------------------
// Scratch (device globals)
// ---------------------------------------------------------------------------
__device__ float g_buf1[4*512*1024];
__device__ float g_buf2[4*768*1024];
__device__ float g_buf3[4*256*1024];
__device__ __align__(16) __nv_bfloat16 g_xh0[4*512*1024];
__device__ __align__(16) __nv_bfloat16 g_xl0[4*512*1024];
__device__ __align__(16) __nv_bfloat16 g_xh1[4*512*1024];
__device__ __align__(16) __nv_bfloat16 g_xl1[4*512*1024];
__device__ __align__(16) __nv_bfloat16 g_qh[4*768*1024];
__device__ __align__(16) __nv_bfloat16 g_ql[4*768*1024];
__device__ __align__(16) __nv_bfloat16 g_Wh[1048576];
__device__ __align__(16) __nv_bfloat16 g_Wl[1048576];

#define OFF_W1 0
#define OFF_WQ (OFF_W1 + 512*512)
#define OFF_WP (OFF_WQ + 768*256)
#define OFF_F1 (OFF_WP + 256*256)
#define OFF_F2 (OFF_F1 + 512*256)
#define OFF_C2 (OFF_F2 + 256*512)

__device__ __forceinline__ void splitf(float v, __nv_bfloat16& h, __nv_bfloat16& l) {
    h = __float2bfloat16(v);
    l = __float2bfloat16(v - __bfloat162float(h));
}
__device__ __forceinline__ void pack2(float x, float y, uint32_t& h, uint32_t& l) {
    __nv_bfloat16 hx, lx, hy, ly;
    splitf(x, hx, lx); splitf(y, hy, ly);
    h = (uint32_t)*(unsigned short*)&hx | ((uint32_t)*(unsigned short*)&hy << 16);
    l = (uint32_t)*(unsigned short*)&lx | ((uint32_t)*(unsigned short*)&ly << 16);
}

// ---------------------------------------------------------------------------
// Fused expansion: quaternion weights -> dense bf16 hi/lo GEMM weights
// ---------------------------------------------------------------------------
__global__ void expand_all_kernel(const float* __restrict__ w0, const float* __restrict__ w1,
                                  const float* __restrict__ w2, const float* __restrict__ w3,
                                  const float* __restrict__ w4, const float* __restrict__ w5,
                                  __nv_bfloat16* __restrict__ Wh, __nv_bfloat16* __restrict__ Wl) {
    const int Couts[6] = {128,192,64,128,64,128};
    const int Cins [6] = {128, 64,64, 64,128,128};
    const int offs [6] = {OFF_W1,OFF_WQ,OFF_WP,OFF_F1,OFF_F2,OFF_C2};
    const float* srcs[6] = {w0,w1,w2,w3,w4,w5};
    int q = blockIdx.y;
    int Cout = Couts[q], Cin = Cins[q];
    const float* w = srcs[q];
    int off = offs[q];
    int total = 16 * Cout * Cin;
    for (int i = blockIdx.x * blockDim.x + threadIdx.x; i < total;
         i += gridDim.x * blockDim.x) {
        int s = i & 3, t = (i >> 2) & 3;
        int rest = i >> 4;
        int ci = rest % Cin, co = rest / Cin;
        float val = c_sgn[t*4 + s] * w[c_cmp[t*4 + s] * Cout * Cin + co * Cin + ci];
        __nv_bfloat16 h, l;
        splitf(val, h, l);
        int idx = off + (co*4 + t) * (4*Cin) + ci*4 + s;
        Wh[idx] = h;
        Wl[idx] = l;
    }
}

// ---------------------------------------------------------------------------
// Plain fp32 -> bf16 hi/lo split (network input x)
// ---------------------------------------------------------------------------
__global__ __launch_bounds__(256) void split_x_kernel(const float* __restrict__ X,
                                                      __nv_bfloat16* __restrict__ H,
                                                      __nv_bfloat16* __restrict__ L) {
    int i = blockIdx.x * 256 + threadIdx.x;
    float4 v = ((const float4*)X)[i];
    __nv_bfloat16 h[4], l[4];
    splitf(v.x, h[0], l[0]); splitf(v.y, h[1], l[1]);
    splitf(v.z, h[2], l[2]); splitf(v.w, h[3], l[3]);
    *(uint2*)(H + (long)i * 4) = *(uint2*)h;
    *(uint2*)(L + (long)i * 4) = *(uint2*)l;
}

// ---------------------------------------------------------------------------
// mma / ldmatrix helpers
// ---------------------------------------------------------------------------
__device__ __forceinline__ void mma16816(float* d, uint32_t a0, uint32_t a1,
                                         uint32_t a2, uint32_t a3,
                                         uint32_t b0, uint32_t b1) {
    asm volatile(
        "mma.sync.aligned.m16n8k16.row.col.f32.bf16.bf16.f32 "
        "{%0,%1,%2,%3}, {%4,%5,%6,%7}, {%8,%9}, {%0,%1,%2,%3};"
        : "+f"(d[0]), "+f"(d[1]), "+f"(d[2]), "+f"(d[3])
        : "r"(a0), "r"(a1), "r"(a2), "r"(a3), "r"(b0), "r"(b1));
}
__device__ __forceinline__ void ldsm4(uint32_t& r0, uint32_t& r1, uint32_t& r2,
                                      uint32_t& r3, uint32_t addr) {
    asm volatile("ldmatrix.sync.aligned.m8n8.x4.shared.b16 {%0,%1,%2,%3}, [%4];"
                 : "=r"(r0), "=r"(r1), "=r"(r2), "=r"(r3) : "r"(addr));
}
__device__ __forceinline__ void ldsm4t(uint32_t& r0, uint32_t& r1, uint32_t& r2,
                                       uint32_t& r3, uint32_t addr) {
    asm volatile("ldmatrix.sync.aligned.m8n8.x4.trans.shared.b16 {%0,%1,%2,%3}, [%4];"
                 : "=r"(r0), "=r"(r1), "=r"(r2), "=r"(r3) : "r"(addr));
}

// ---------------------------------------------------------------------------
// HMMA bf16-split GEMM (R10 version) + optional split-plane epilogue:
// if Yh != nullptr, writes bf16 hi/lo planes (bias included) instead of fp32.
// ---------------------------------------------------------------------------
#define APITCH 40
#define BPITCH 136
#define A_PLANE (64*APITCH)
#define B_PLANE (32*BPITCH)
#define GBUF (2*A_PLANE + 2*B_PLANE)
#define GEMM_SMEM (2*GBUF*2)

__global__ __launch_bounds__(128) void mma_gemm_kernel(
    const __nv_bfloat16* __restrict__ Wh, const __nv_bfloat16* __restrict__ Wl,
    const __nv_bfloat16* __restrict__ Xh, const __nv_bfloat16* __restrict__ Xl,
    float* __restrict__ Y, __nv_bfloat16* __restrict__ Yh, __nv_bfloat16* __restrict__ Yl,
    const float* __restrict__ bias, int M, int K, long sX, long sY)
{
    extern __shared__ __nv_bfloat16 smd[];
    const uint32_t smem_base = (uint32_t)__cvta_generic_to_shared(smd);

    const int tid = threadIdx.x;
    const int wid = tid >> 5, lane = tid & 31;
    const int wm = wid & 1, wn = wid >> 1;
    const int g = lane >> 2, tg = lane & 3;
    const int mo = blockIdx.y * 64, no = blockIdx.x * 128;
    const __nv_bfloat16* Xhb = Xh + blockIdx.z * sX;
    const __nv_bfloat16* Xlb = Xl + blockIdx.z * sX;

    const int am = tid >> 1, ak = (tid & 1) * 16;
    const int bcol = (tid & 31) * 4;
    const int bk0 = (tid >> 5) * 2;

    float acc[2][8][4] = {};
    const int nch = K >> 5;

    uint4 awh[2], awl[2];
    uint2 bh[4][2], bl[4][2];

#define LOAD_REGS(kt)                                                            \
    {                                                                            \
        const __nv_bfloat16* Ah = Wh + (long)(mo + am) * K + (kt) + ak;          \
        const __nv_bfloat16* Al = Wl + (long)(mo + am) * K + (kt) + ak;          \
        awh[0] = *(const uint4*)Ah; awh[1] = *(const uint4*)(Ah + 8);            \
        awl[0] = *(const uint4*)Al; awl[1] = *(const uint4*)(Al + 8);            \
        _Pragma("unroll")                                                        \
        for (int I = 0; I < 4; I++) {                                            \
            int kr = (kt) + bk0 + 8 * I;                                         \
            const __nv_bfloat16* Bh = Xhb + (long)kr * 1024 + no + bcol;         \
            const __nv_bfloat16* Bl = Xlb + (long)kr * 1024 + no + bcol;         \
            bh[I][0] = *(const uint2*)Bh; bh[I][1] = *(const uint2*)(Bh + 1024); \
            bl[I][0] = *(const uint2*)Bl; bl[I][1] = *(const uint2*)(Bl + 1024); \
        }                                                                        \
    }

#define STORE_SMEM(buf)                                                          \
    {                                                                            \
        __nv_bfloat16* base = smd + (buf) * GBUF;                                \
        uint32_t* dH = (uint32_t*)(base + am * APITCH + ak);                     \
        uint32_t* dL = (uint32_t*)(base + A_PLANE + am * APITCH + ak);           \
        *(uint4*)dH = awh[0]; *(uint4*)(dH + 4) = awh[1];                        \
        *(uint4*)dL = awl[0]; *(uint4*)(dL + 4) = awl[1];                        \
        __nv_bfloat16* BH = base + 2 * A_PLANE;                                  \
        __nv_bfloat16* BL = base + 2 * A_PLANE + B_PLANE;                        \
        _Pragma("unroll")                                                        \
        for (int I = 0; I < 4; I++) {                                            \
            int kr = bk0 + 8 * I;                                                \
            *(uint2*)(BH + kr * BPITCH + bcol)       = bh[I][0];                 \
            *(uint2*)(BH + (kr + 1) * BPITCH + bcol) = bh[I][1];                 \
            *(uint2*)(BL + kr * BPITCH + bcol)       = bl[I][0];                 \
            *(uint2*)(BL + (kr + 1) * BPITCH + bcol) = bl[I][1];                 \
        }                                                                        \
    }

    LOAD_REGS(0);
    STORE_SMEM(0);
    if (nch > 1) LOAD_REGS(32);
    __syncthreads();

    const int a_row_l = lane & 15;
    const int a_khalf = (lane >> 4) * 8;
    const int b_krow  = (lane & 7) + 8 * ((lane >> 3) & 1);
    const int b_nhalf = (lane >> 4) * 8;

    for (int ch = 0; ch < nch; ch++) {
        if (ch + 1 < nch) STORE_SMEM((ch + 1) & 1);
        if (ch + 2 < nch) LOAD_REGS((ch + 2) * 32);

        uint32_t bufu = (uint32_t)((ch & 1) * GBUF) * 2u;
        uint32_t AH = smem_base + bufu;
        uint32_t ALo = AH + A_PLANE * 2;
        uint32_t BH = AH + 4 * A_PLANE;
        uint32_t BLo = BH + B_PLANE * 2;

#pragma unroll
        for (int k0 = 0; k0 < 32; k0 += 16) {
            uint32_t ah[2][4], al[2][4];
#pragma unroll
            for (int mt = 0; mt < 2; mt++) {
                int rowb = wm * 32 + mt * 16;
                uint32_t off = (uint32_t)((rowb + a_row_l) * APITCH + k0 + a_khalf) * 2u;
                ldsm4(ah[mt][0], ah[mt][1], ah[mt][2], ah[mt][3], AH + off);
                ldsm4(al[mt][0], al[mt][1], al[mt][2], al[mt][3], ALo + off);
            }
#pragma unroll
            for (int ntp = 0; ntp < 4; ntp++) {
                int nbase = wn * 64 + ntp * 16;
                uint32_t off = (uint32_t)((k0 + b_krow) * BPITCH + nbase + b_nhalf) * 2u;
                uint32_t bh0, bh1, bh2, bh3, bl0, bl1, bl2, bl3;
                ldsm4t(bh0, bh1, bh2, bh3, BH + off);
                ldsm4t(bl0, bl1, bl2, bl3, BLo + off);
#pragma unroll
                for (int mt = 0; mt < 2; mt++) {
                    float* d0 = acc[mt][ntp * 2];
                    float* d1 = acc[mt][ntp * 2 + 1];
                    mma16816(d0, ah[mt][0], ah[mt][1], ah[mt][2], ah[mt][3], bh0, bh1);
                    mma16816(d0, al[mt][0], al[mt][1], al[mt][2], al[mt][3], bh0, bh1);
                    mma16816(d0, ah[mt][0], ah[mt][1], ah[mt][2], ah[mt][3], bl0, bl1);
                    mma16816(d1, ah[mt][0], ah[mt][1], ah[mt][2], ah[mt][3], bh2, bh3);
                    mma16816(d1, al[mt][0], al[mt][1], al[mt][2], al[mt][3], bh2, bh3);
                    mma16816(d1, ah[mt][0], ah[mt][1], ah[mt][2], ah[mt][3], bl2, bl3);
                }
            }
        }
        if (ch + 1 < nch) __syncthreads();
    }

    if (Yh) {
        __nv_bfloat16* Yhb = Yh + blockIdx.z * sY;
        __nv_bfloat16* Ylb = Yl + blockIdx.z * sY;
#pragma unroll
        for (int mt = 0; mt < 2; mt++) {
            int r0 = mo + wm * 32 + mt * 16 + g;
            int r1 = r0 + 8;
            float bv0 = bias ? bias[r0] : 0.f;
            float bv1 = bias ? bias[r1] : 0.f;
#pragma unroll
            for (int nt = 0; nt < 8; nt++) {
                int c = no + wn * 64 + nt * 8 + 2 * tg;
                float* d = acc[mt][nt];
                uint32_t h01, l01, h23, l23;
                pack2(d[0] + bv0, d[1] + bv0, h01, l01);
                pack2(d[2] + bv1, d[3] + bv1, h23, l23);
                *(uint32_t*)(Yhb + (long)r0 * 1024 + c) = h01;
                *(uint32_t*)(Ylb + (long)r0 * 1024 + c) = l01;
                *(uint32_t*)(Yhb + (long)r1 * 1024 + c) = h23;
                *(uint32_t*)(Ylb + (long)r1 * 1024 + c) = l23;
            }
        }
    } else {
        float* Yb = Y + blockIdx.z * sY;
#pragma unroll
        for (int mt = 0; mt < 2; mt++) {
            int r0 = mo + wm * 32 + mt * 16 + g;
            int r1 = r0 + 8;
            float bv0 = bias ? bias[r0] : 0.f;
            float bv1 = bias ? bias[r1] : 0.f;
#pragma unroll
            for (int nt = 0; nt < 8; nt++) {
                int c = no + wn * 64 + nt * 8 + 2 * tg;
                float* d = acc[mt][nt];
                *(float2*)(Yb + (long)r0 * 1024 + c) = make_float2(d[0] + bv0, d[1] + bv0);
                *(float2*)(Yb + (long)r1 * 1024 + c) = make_float2(d[2] + bv1, d[3] + bv1);
            }
        }
    }
#undef LOAD_REGS
#undef STORE_SMEM
}

// ---------------------------------------------------------------------------
// Fused BN: stats + apply + bf16 split (unchanged)
// ---------------------------------------------------------------------------
__global__ __launch_bounds__(256) void bn_fused_split(
    const float* __restrict__ X, __nv_bfloat16* __restrict__ H,
    __nv_bfloat16* __restrict__ L,
    const float* __restrict__ g, const float* __restrict__ be,
    long bsX, long bsP, int relu)
{
    int m = blockIdx.x, tid = threadIdx.x;
    float4 v[4];
    float s = 0.f, sq = 0.f;
#pragma unroll
    for (int b = 0; b < 4; b++) {
        v[b] = *(const float4*)(X + b * bsX + (long)m * 1024 + tid * 4);
        s  += v[b].x + v[b].y + v[b].z + v[b].w;
        sq += v[b].x*v[b].x + v[b].y*v[b].y + v[b].z*v[b].z + v[b].w*v[b].w;
    }
#pragma unroll
    for (int o = 16; o; o >>= 1) {
        s  += __shfl_xor_sync(0xffffffffu, s, o);
        sq += __shfl_xor_sync(0xffffffffu, sq, o);
    }
    __shared__ float ps[8], pq[8], bsc[1], bsh[1];
    if ((tid & 31) == 0) { ps[tid >> 5] = s; pq[tid >> 5] = sq; }
    __syncthreads();
    if (tid == 0) {
        s = 0.f; sq = 0.f;
#pragma unroll
        for (int i = 0; i < 8; i++) { s += ps[i]; sq += pq[i]; }
        float mean = s * (1.f / 4096.f);
        float var  = sq * (1.f / 4096.f) - mean * mean;
        float rstd = rsqrtf(var + 1e-5f);
        float sc = g[m] * rstd;
        bsc[0] = sc;
        bsh[0] = be[m] - mean * sc;
    }
    __syncthreads();
    float sc = bsc[0], sh = bsh[0];
#pragma unroll
    for (int b = 0; b < 4; b++) {
        float4 w = v[b];
        w.x = w.x * sc + sh; w.y = w.y * sc + sh;
        w.z = w.z * sc + sh; w.w = w.w * sc + sh;
        if (relu) {
            w.x = fmaxf(w.x, 0.f); w.y = fmaxf(w.y, 0.f);
            w.z = fmaxf(w.z, 0.f); w.w = fmaxf(w.w, 0.f);
        }
        __nv_bfloat16 h[4], l[4];
        splitf(w.x, h[0], l[0]); splitf(w.y, h[1], l[1]);
        splitf(w.z, h[2], l[2]); splitf(w.w, h[3], l[3]);
        long o = (long)b * bsP + (long)m * 1024 + tid * 4;
        *(uint2*)(H + o) = *(uint2*)h;
        *(uint2*)(L + o) = *(uint2*)l;
    }
}

__global__ __launch_bounds__(256) void bn_fused_out(
    const float* __restrict__ X, float* __restrict__ Y,
    const float* __restrict__ g, const float* __restrict__ be,
    long bsX, long bsY, int relu)
{
    int m = blockIdx.x, tid = threadIdx.x;
    float4 v[4];
    float s = 0.f, sq = 0.f;
#pragma unroll
    for (int b = 0; b < 4; b++) {
        v[b] = *(const float4*)(X + b * bsX + (long)m * 1024 + tid * 4);
        s  += v[b].x + v[b].y + v[b].z + v[b].w;
        sq += v[b].x*v[b].x + v[b].y*v[b].y + v[b].z*v[b].z + v[b].w*v[b].w;
    }
#pragma unroll
    for (int o = 16; o; o >>= 1) {
        s  += __shfl_xor_sync(0xffffffffu, s, o);
        sq += __shfl_xor_sync(0xffffffffu, sq, o);
    }
    __shared__ float ps[8], pq[8], bsc[1], bsh[1];
    if ((tid & 31) == 0) { ps[tid >> 5] = s; pq[tid >> 5] = sq; }
    __syncthreads();
    if (tid == 0) {
        s = 0.f; sq = 0.f;
#pragma unroll
        for (int i = 0; i < 8; i++) { s += ps[i]; sq += pq[i]; }
        float mean = s * (1.f / 4096.f);
        float var  = sq * (1.f / 4096.f) - mean * mean;
        float rstd = rsqrtf(var + 1e-5f);
        float sc = g[m] * rstd;
        bsc[0] = sc;
        bsh[0] = be[m] - mean * sc;
    }
    __syncthreads();
    float sc = bsc[0], sh = bsh[0];
#pragma unroll
    for (int b = 0; b < 4; b++) {
        float4 w = v[b];
        w.x = w.x * sc + sh; w.y = w.y * sc + sh;
        w.z = w.z * sc + sh; w.w = w.w * sc + sh;
        if (relu) {
            w.x = fmaxf(w.x, 0.f); w.y = fmaxf(w.y, 0.f);
            w.z = fmaxf(w.z, 0.f); w.w = fmaxf(w.w, 0.f);
        }
        *(float4*)(Y + (long)b * bsY + (long)m * 1024 + tid * 4) = w;
    }
}

// ---------------------------------------------------------------------------
// Tensor-core flash attention — inputs are PRE-SPLIT bf16 planes (qkv GEMM
// epilogue). Loaders are pure copies; all fragment math identical to R10.
// ---------------------------------------------------------------------------
#define QP 24
#define KP 24
#define VP 136

__global__ __launch_bounds__(256) void attn_kernel(
    const __nv_bfloat16* __restrict__ Hp, const __nv_bfloat16* __restrict__ Lp,
    float* __restrict__ O) {
    __shared__ __nv_bfloat16 QH[32*QP], QL[32*QP];
    __shared__ __nv_bfloat16 KH[128*KP], KL[128*KP];
    __shared__ __nv_bfloat16 VH[16*VP], VL[16*VP];
    __shared__ float redmax[4][32], redsum[4][32];
    __shared__ float Of[4][2][16][17];
    __shared__ float rsinv[32];

    int b = blockIdx.z, head = blockIdx.y >> 2, t = blockIdx.y & 3;
    int r0 = blockIdx.x * 32;
    const __nv_bfloat16* Hb = Hp + (long)b * 768 * 1024;
    const __nv_bfloat16* Lb = Lp + (long)b * 768 * 1024;
    int tid = threadIdx.x, lane = tid & 31, wid = tid >> 5;
    int wm = wid & 1, wn = wid >> 1;
    int g = lane >> 2, tg = lane & 3;

    for (int i = tid; i < 512; i += 256) {
        int dd = i >> 5, q = i & 31;
        long off = (long)(head * 192 + dd * 4 + t) * 1024 + r0 + q;
        QH[q * QP + dd] = Hb[off];
        QL[q * QP + dd] = Lb[off];
    }
    __syncthreads();

    uint32_t qh[4], ql[4];
    {
        int r = wm * 16 + g;
        qh[0] = *(uint32_t*)&QH[r * QP + 2*tg];
        qh[1] = *(uint32_t*)&QH[(r + 8) * QP + 2*tg];
        qh[2] = *(uint32_t*)&QH[r * QP + 2*tg + 8];
        qh[3] = *(uint32_t*)&QH[(r + 8) * QP + 2*tg + 8];
        ql[0] = *(uint32_t*)&QL[r * QP + 2*tg];
        ql[1] = *(uint32_t*)&QL[(r + 8) * QP + 2*tg];
        ql[2] = *(uint32_t*)&QL[r * QP + 2*tg + 8];
        ql[3] = *(uint32_t*)&QL[(r + 8) * QP + 2*tg + 8];
    }

    float od[2][4] = {};
    float rm_lo = -1e30f, rm_hi = -1e30f, rs_lo = 0.f, rs_hi = 0.f;
    const float sc = 0.25f;
    const int rlo = wm * 16 + g, rhi = rlo + 8;

    for (int ch = 0; ch < 8; ch++) {
        __syncthreads();
        for (int i = tid; i < 2048; i += 256) {
            int dd = i >> 7, key = i & 127;
            long rk = (long)(head * 192 + 64 + dd * 4 + t) * 1024 + ch * 128 + key;
            KH[key * KP + dd] = Hb[rk];
            KL[key * KP + dd] = Lb[rk];
            long rv = (long)(head * 192 + 128 + dd * 4 + t) * 1024 + ch * 128 + key;
            VH[dd * VP + key] = Hb[rv];
            VL[dd * VP + key] = Lb[rv];
        }
        __syncthreads();

        float sacc[4][4] = {};
#pragma unroll
        for (int nt = 0; nt < 4; nt++) {
            int nb = wn * 32 + nt * 8 + g;
            uint32_t kb0 = *(uint32_t*)&KH[nb * KP + 2*tg];
            uint32_t kb1 = *(uint32_t*)&KH[nb * KP + 2*tg + 8];
            uint32_t kc0 = *(uint32_t*)&KL[nb * KP + 2*tg];
            uint32_t kc1 = *(uint32_t*)&KL[nb * KP + 2*tg + 8];
            mma16816(sacc[nt], qh[0], qh[1], qh[2], qh[3], kb0, kb1);
            mma16816(sacc[nt], ql[0], ql[1], ql[2], ql[3], kb0, kb1);
            mma16816(sacc[nt], qh[0], qh[1], qh[2], qh[3], kc0, kc1);
        }
        float mx_lo = -1e30f, mx_hi = -1e30f;
#pragma unroll
        for (int nt = 0; nt < 4; nt++) {
            sacc[nt][0] *= sc; sacc[nt][1] *= sc;
            sacc[nt][2] *= sc; sacc[nt][3] *= sc;
            mx_lo = fmaxf(mx_lo, fmaxf(sacc[nt][0], sacc[nt][1]));
            mx_hi = fmaxf(mx_hi, fmaxf(sacc[nt][2], sacc[nt][3]));
        }
        mx_lo = fmaxf(mx_lo, __shfl_xor_sync(0xffffffffu, mx_lo, 1));
        mx_lo = fmaxf(mx_lo, __shfl_xor_sync(0xffffffffu, mx_lo, 2));
        mx_hi = fmaxf(mx_hi, __shfl_xor_sync(0xffffffffu, mx_hi, 1));
        mx_hi = fmaxf(mx_hi, __shfl_xor_sync(0xffffffffu, mx_hi, 2));
        if (tg == 0) { redmax[wn][rlo] = mx_lo; redmax[wn][rhi] = mx_hi; }
        __syncthreads();

        float cm_lo = fmaxf(fmaxf(redmax[0][rlo], redmax[1][rlo]),
                            fmaxf(redmax[2][rlo], redmax[3][rlo]));
        float cm_hi = fmaxf(fmaxf(redmax[0][rhi], redmax[1][rhi]),
                            fmaxf(redmax[2][rhi], redmax[3][rhi]));
        float nm_lo = fmaxf(rm_lo, cm_lo), f_lo = __expf(rm_lo - nm_lo);
        float nm_hi = fmaxf(rm_hi, cm_hi), f_hi = __expf(rm_hi - nm_hi);
        rm_lo = nm_lo; rm_hi = nm_hi;

        float e[4][4];
        float sum_lo = 0.f, sum_hi = 0.f;
#pragma unroll
        for (int nt = 0; nt < 4; nt++) {
            e[nt][0] = __expf(sacc[nt][0] - nm_lo);
            e[nt][1] = __expf(sacc[nt][1] - nm_lo);
            e[nt][2] = __expf(sacc[nt][2] - nm_hi);
            e[nt][3] = __expf(sacc[nt][3] - nm_hi);
            sum_lo += e[nt][0] + e[nt][1];
            sum_hi += e[nt][2] + e[nt][3];
        }
        sum_lo += __shfl_xor_sync(0xffffffffu, sum_lo, 1);
        sum_lo += __shfl_xor_sync(0xffffffffu, sum_lo, 2);
        sum_hi += __shfl_xor_sync(0xffffffffu, sum_hi, 1);
        sum_hi += __shfl_xor_sync(0xffffffffu, sum_hi, 2);
        if (tg == 0) { redsum[wn][rlo] = sum_lo; redsum[wn][rhi] = sum_hi; }
        __syncthreads();

        rs_lo = rs_lo * f_lo + redsum[0][rlo] + redsum[1][rlo] + redsum[2][rlo] + redsum[3][rlo];
        rs_hi = rs_hi * f_hi + redsum[0][rhi] + redsum[1][rhi] + redsum[2][rhi] + redsum[3][rhi];

#pragma unroll
        for (int dn = 0; dn < 2; dn++) {
            od[dn][0] *= f_lo; od[dn][1] *= f_lo;
            od[dn][2] *= f_hi; od[dn][3] *= f_hi;
        }
        uint32_t ph[2][4], pl[2][4];
#pragma unroll
        for (int ks = 0; ks < 2; ks++) {
            pack2(e[2*ks][0],   e[2*ks][1],   ph[ks][0], pl[ks][0]);
            pack2(e[2*ks][2],   e[2*ks][3],   ph[ks][1], pl[ks][1]);
            pack2(e[2*ks+1][0], e[2*ks+1][1], ph[ks][2], pl[ks][2]);
            pack2(e[2*ks+1][2], e[2*ks+1][3], ph[ks][3], pl[ks][3]);
        }
#pragma unroll
        for (int ks = 0; ks < 2; ks++) {
#pragma unroll
            for (int dn = 0; dn < 2; dn++) {
                int vrow = dn * 8 + g;
                int kk = wn * 32 + ks * 16;
                uint32_t vb0 = *(uint32_t*)&VH[vrow * VP + kk + 2*tg];
                uint32_t vb1 = *(uint32_t*)&VH[vrow * VP + kk + 2*tg + 8];
                uint32_t vc0 = *(uint32_t*)&VL[vrow * VP + kk + 2*tg];
                uint32_t vc1 = *(uint32_t*)&VL[vrow * VP + kk + 2*tg + 8];
                mma16816(od[dn], ph[ks][0], ph[ks][1], ph[ks][2], ph[ks][3], vb0, vb1);
                mma16816(od[dn], pl[ks][0], pl[ks][1], pl[ks][2], pl[ks][3], vb0, vb1);
                mma16816(od[dn], ph[ks][0], ph[ks][1], ph[ks][2], ph[ks][3], vc0, vc1);
            }
        }
    }

#pragma unroll
    for (int dn = 0; dn < 2; dn++) {
        Of[wn][wm][g][dn*8 + 2*tg]       = od[dn][0];
        Of[wn][wm][g][dn*8 + 2*tg + 1]   = od[dn][1];
        Of[wn][wm][g+8][dn*8 + 2*tg]     = od[dn][2];
        Of[wn][wm][g+8][dn*8 + 2*tg + 1] = od[dn][3];
    }
    if (tg == 0 && wn == 0) {
        rsinv[rlo] = 1.f / rs_lo;
        rsinv[rhi] = 1.f / rs_hi;
    }
    __syncthreads();

    int q = tid & 31, dd = tid >> 5;
    float inv = rsinv[q];
    int qm = q >> 4, qr = q & 15;
    float* Ob = O + (long)b * 256 * 1024;
#pragma unroll
    for (int h2 = 0; h2 < 2; h2++) {
        int D = dd + h2 * 8;
        float v = (Of[0][qm][qr][D] + Of[1][qm][qr][D] +
                   Of[2][qm][qr][D] + Of[3][qm][qr][D]) * inv;
        Ob[(head * 64 + D * 4 + t) * 1024 + r0 + q] = v;
    }
}

// ---------------------------------------------------------------------------
// PE conv + residual; 4 pixels per thread (shared window loads).
// Emits bf16 hi/lo split planes. grid = 1024 blocks x 256 threads.
// ---------------------------------------------------------------------------
__global__ __launch_bounds__(256) void pe_kernel(
    const float* __restrict__ I, const float* __restrict__ pw,
    const float* __restrict__ pb,
    __nv_bfloat16* __restrict__ H, __nv_bfloat16* __restrict__ L, long bsP)
{
    int unit = blockIdx.x * 256 + threadIdx.x;   // 262144 units, 4 px each
    int p4 = unit & 255;
    int m  = (unit >> 8) & 255;
    int b  = unit >> 16;
    int p  = p4 * 4;
    int h = p >> 5, w0 = p & 31;                 // 4 px: (h, w0..w0+3)
    int co = m >> 2, t = m & 3, g = co >> 2;
    const float* Ib = I + (long)b * 256 * 1024;

    float4 res = *(const float4*)(Ib + m * 1024 + p);
    float acc[4] = {res.x + pb[m], res.y + pb[m], res.z + pb[m], res.w + pb[m]};

#pragma unroll
    for (int s = 0; s < 4; s++) {
        float sg = c_sgn[t * 4 + s];
        const float* wc = pw + ((long)c_cmp[t * 4 + s] * 64 + co) * 36;
        float part[4] = {0.f, 0.f, 0.f, 0.f};
#pragma unroll
        for (int cil = 0; cil < 4; cil++) {
            const float* in = Ib + ((g * 4 + cil) * 4 + s) * 1024;
            const float* wk = wc + cil * 9;
#pragma unroll
            for (int kh = 0; kh < 3; kh++) {
                int hh = h + kh - 1;
                if (hh < 0 || hh > 31) continue;
                const float* row = in + hh * 32;
                float v[6];
                v[0] = (w0 - 1 >= 0) ? row[w0 - 1] : 0.f;
                v[1] = row[w0];
                v[2] = row[w0 + 1];
                v[3] = row[w0 + 2];
                v[4] = row[w0 + 3];
                v[5] = (w0 + 4 <= 31) ? row[w0 + 4] : 0.f;
                float wk0 = wk[kh * 3], wk1 = wk[kh * 3 + 1], wk2 = wk[kh * 3 + 2];
#pragma unroll
                for (int j = 0; j < 4; j++)
                    part[j] += v[j] * wk0 + v[j + 1] * wk1 + v[j + 2] * wk2;
            }
        }
#pragma unroll
        for (int j = 0; j < 4; j++) acc[j] += sg * part[j];
    }

    __nv_bfloat16 hh4[4], ll4[4];
#pragma unroll
    for (int j = 0; j < 4; j++) splitf(acc[j], hh4[j], ll4[j]);
    long o = (long)b * bsP + (long)m * 1024 + p;
    *(uint2*)(H + o) = *(uint2*)hh4;
    *(uint2*)(L + o) = *(uint2*)ll4;
}

// ---------------------------------------------------------------------------
extern "C" void kernel_launch(void* const* d_in, const int* in_sizes, int n_in,
                              void* d_out, int out_size) {
    const float* x      = (const float*)d_in[0];
    const float* cv1_w  = (const float*)d_in[1];
    const float* bn1_g  = (const float*)d_in[2];
    const float* bn1_b  = (const float*)d_in[3];
    const float* qkv_w  = (const float*)d_in[4];
    const float* qkv_b  = (const float*)d_in[5];
    const float* proj_w = (const float*)d_in[6];
    const float* proj_b = (const float*)d_in[7];
    const float* pe_w   = (const float*)d_in[8];
    const float* pe_b   = (const float*)d_in[9];
    const float* ang    = (const float*)d_in[10];
    const float* anb    = (const float*)d_in[11];
    const float* f1w    = (const float*)d_in[12];
    const float* f1g    = (const float*)d_in[13];
    const float* f1b    = (const float*)d_in[14];
    const float* f2w    = (const float*)d_in[15];
    const float* f2g    = (const float*)d_in[16];
    const float* f2b    = (const float*)d_in[17];
    const float* cv2_w  = (const float*)d_in[18];
    const float* bn2_g  = (const float*)d_in[19];
    const float* bn2_b  = (const float*)d_in[20];

    float *buf1, *buf2, *buf3;
    __nv_bfloat16 *xh0, *xl0, *xh1, *xl1, *qh, *ql, *Wh, *Wl;
    cudaGetSymbolAddress((void**)&buf1, g_buf1);
    cudaGetSymbolAddress((void**)&buf2, g_buf2);
    cudaGetSymbolAddress((void**)&buf3, g_buf3);
    cudaGetSymbolAddress((void**)&xh0,  g_xh0);
    cudaGetSymbolAddress((void**)&xl0,  g_xl0);
    cudaGetSymbolAddress((void**)&xh1,  g_xh1);
    cudaGetSymbolAddress((void**)&xl1,  g_xl1);
    cudaGetSymbolAddress((void**)&qh,   g_qh);
    cudaGetSymbolAddress((void**)&ql,   g_ql);
    cudaGetSymbolAddress((void**)&Wh,   g_Wh);
    cudaGetSymbolAddress((void**)&Wl,   g_Wl);

    const long S512 = 512L * 1024, S768 = 768L * 1024, S256 = 256L * 1024;

    cudaFuncSetAttribute(mma_gemm_kernel,
                         cudaFuncAttributeMaxDynamicSharedMemorySize, GEMM_SMEM);

    expand_all_kernel<<<dim3(32, 6), 256>>>(cv1_w, qkv_w, proj_w, f1w, f2w, cv2_w, Wh, Wl);
    split_x_kernel<<<2048, 256>>>(x, xh0, xl0);

    // cv1 + iqbn(+relu) -> P1 (512 rows)
    mma_gemm_kernel<<<dim3(8, 8, 4), 128, GEMM_SMEM>>>(Wh + OFF_W1, Wl + OFF_W1, xh0, xl0,
                                                        buf1, nullptr, nullptr, nullptr,
                                                        512, 512, S512, S512);
    bn_fused_split<<<512, 256>>>(buf1, xh1, xl1, bn1_g, bn1_b, S512, S512, 1);

    // qkv -> split planes (bias fused)
    mma_gemm_kernel<<<dim3(8, 12, 4), 128, GEMM_SMEM>>>(Wh + OFF_WQ, Wl + OFF_WQ, xh1, xl1,
                                                         nullptr, qh, ql, qkv_b,
                                                         768, 256, S512, S768);

    // attention (tensor cores, pre-split inputs)
    attn_kernel<<<dim3(32, 16, 4), 256>>>(qh, ql, buf3);

    // pe conv + residual -> P0 (4 px/thread)
    pe_kernel<<<1024, 256>>>(buf3, pe_w, pe_b, xh0, xl0, S512);

    // proj + attn_norm -> P0
    mma_gemm_kernel<<<dim3(8, 4, 4), 128, GEMM_SMEM>>>(Wh + OFF_WP, Wl + OFF_WP, xh0, xl0,
                                                        buf3, nullptr, nullptr, proj_b,
                                                        256, 256, S512, S256);
    bn_fused_split<<<256, 256>>>(buf3, xh0, xl0, ang, anb, S256, S512, 0);

    // ffn1 + bn(+relu) -> P0
    mma_gemm_kernel<<<dim3(8, 8, 4), 128, GEMM_SMEM>>>(Wh + OFF_F1, Wl + OFF_F1, xh0, xl0,
                                                        buf2, nullptr, nullptr, nullptr,
                                                        512, 256, S512, S512);
    bn_fused_split<<<512, 256>>>(buf2, xh0, xl0, f1g, f1b, S512, S512, 1);

    // ffn2 + bn -> P1 rows 0..255 (rows 256..511 = b from bn1)
    mma_gemm_kernel<<<dim3(8, 4, 4), 128, GEMM_SMEM>>>(Wh + OFF_F2, Wl + OFF_F2, xh0, xl0,
                                                        buf3, nullptr, nullptr, nullptr,
                                                        256, 512, S512, S256);
    bn_fused_split<<<256, 256>>>(buf3, xh1, xl1, f2g, f2b, S256, S512, 0);

    // cv2 on concat + bn + relu -> d_out
    mma_gemm_kernel<<<dim3(8, 8, 4), 128, GEMM_SMEM>>>(Wh + OFF_C2, Wl + OFF_C2, xh1, xl1,
                                                        buf2, nullptr, nullptr, nullptr,
                                                        512, 512, S512, S512);
    bn_fused_out<<<512, 256>>>(buf2, (float*)d_out, bn2_g, bn2_b, S512, S512, 1);
}

// round 12
// speedup vs baseline: 1.1355x; 1.1355x over previous
#include <cuda_runtime.h>
#include <cuda_bf16.h>
#include <cstdint>

// ---------------------------------------------------------------------------
// Quaternion Hamilton-product tables
// ---------------------------------------------------------------------------
__constant__ int   c_cmp[16] = {0,1,2,3,  1,0,3,2,  2,3,0,1,  3,2,1,0};
__constant__ float c_sgn[16] = {1.f,-1.f,-1.f,-1.f,
                                1.f, 1.f, 1.f,-1.f,
                                1.f,-1.f, 1.f, 1.f,
                                1.f, 1.f,-1.f, 1.f};

// ---------------------------------------------------------------------------
// Scratch (device globals)
// ---------------------------------------------------------------------------
__device__ float g_buf1[4*512*1024];
__device__ float g_buf2[4*768*1024];
__device__ float g_buf3[4*256*1024];
__device__ __align__(16) __nv_bfloat16 g_xh0[4*512*1024];
__device__ __align__(16) __nv_bfloat16 g_xl0[4*512*1024];
__device__ __align__(16) __nv_bfloat16 g_xh1[4*512*1024];
__device__ __align__(16) __nv_bfloat16 g_xl1[4*512*1024];
__device__ __align__(16) __nv_bfloat16 g_qh[4*768*1024];
__device__ __align__(16) __nv_bfloat16 g_ql[4*768*1024];
__device__ __align__(16) __nv_bfloat16 g_Wh[1048576];
__device__ __align__(16) __nv_bfloat16 g_Wl[1048576];

#define OFF_W1 0
#define OFF_WQ (OFF_W1 + 512*512)
#define OFF_WP (OFF_WQ + 768*256)
#define OFF_F1 (OFF_WP + 256*256)
#define OFF_F2 (OFF_F1 + 512*256)
#define OFF_C2 (OFF_F2 + 256*512)

__device__ __forceinline__ void splitf(float v, __nv_bfloat16& h, __nv_bfloat16& l) {
    h = __float2bfloat16(v);
    l = __float2bfloat16(v - __bfloat162float(h));
}
__device__ __forceinline__ void pack2(float x, float y, uint32_t& h, uint32_t& l) {
    __nv_bfloat16 hx, lx, hy, ly;
    splitf(x, hx, lx); splitf(y, hy, ly);
    h = (uint32_t)*(unsigned short*)&hx | ((uint32_t)*(unsigned short*)&hy << 16);
    l = (uint32_t)*(unsigned short*)&lx | ((uint32_t)*(unsigned short*)&ly << 16);
}

// ---------------------------------------------------------------------------
// Fused expansion: quaternion weights -> dense bf16 hi/lo GEMM weights
// ---------------------------------------------------------------------------
__global__ void expand_all_kernel(const float* __restrict__ w0, const float* __restrict__ w1,
                                  const float* __restrict__ w2, const float* __restrict__ w3,
                                  const float* __restrict__ w4, const float* __restrict__ w5,
                                  __nv_bfloat16* __restrict__ Wh, __nv_bfloat16* __restrict__ Wl) {
    const int Couts[6] = {128,192,64,128,64,128};
    const int Cins [6] = {128, 64,64, 64,128,128};
    const int offs [6] = {OFF_W1,OFF_WQ,OFF_WP,OFF_F1,OFF_F2,OFF_C2};
    const float* srcs[6] = {w0,w1,w2,w3,w4,w5};
    int q = blockIdx.y;
    int Cout = Couts[q], Cin = Cins[q];
    const float* w = srcs[q];
    int off = offs[q];
    int total = 16 * Cout * Cin;
    for (int i = blockIdx.x * blockDim.x + threadIdx.x; i < total;
         i += gridDim.x * blockDim.x) {
        int s = i & 3, t = (i >> 2) & 3;
        int rest = i >> 4;
        int ci = rest % Cin, co = rest / Cin;
        float val = c_sgn[t*4 + s] * w[c_cmp[t*4 + s] * Cout * Cin + co * Cin + ci];
        __nv_bfloat16 h, l;
        splitf(val, h, l);
        int idx = off + (co*4 + t) * (4*Cin) + ci*4 + s;
        Wh[idx] = h;
        Wl[idx] = l;
    }
}

// ---------------------------------------------------------------------------
// Plain fp32 -> bf16 hi/lo split (used for input x AND for qkv output)
// ---------------------------------------------------------------------------
__global__ __launch_bounds__(256) void split_x_kernel(const float* __restrict__ X,
                                                      __nv_bfloat16* __restrict__ H,
                                                      __nv_bfloat16* __restrict__ L) {
    int i = blockIdx.x * 256 + threadIdx.x;
    float4 v = ((const float4*)X)[i];
    __nv_bfloat16 h[4], l[4];
    splitf(v.x, h[0], l[0]); splitf(v.y, h[1], l[1]);
    splitf(v.z, h[2], l[2]); splitf(v.w, h[3], l[3]);
    *(uint2*)(H + (long)i * 4) = *(uint2*)h;
    *(uint2*)(L + (long)i * 4) = *(uint2*)l;
}

// ---------------------------------------------------------------------------
// mma / ldmatrix helpers
// ---------------------------------------------------------------------------
__device__ __forceinline__ void mma16816(float* d, uint32_t a0, uint32_t a1,
                                         uint32_t a2, uint32_t a3,
                                         uint32_t b0, uint32_t b1) {
    asm volatile(
        "mma.sync.aligned.m16n8k16.row.col.f32.bf16.bf16.f32 "
        "{%0,%1,%2,%3}, {%4,%5,%6,%7}, {%8,%9}, {%0,%1,%2,%3};"
        : "+f"(d[0]), "+f"(d[1]), "+f"(d[2]), "+f"(d[3])
        : "r"(a0), "r"(a1), "r"(a2), "r"(a3), "r"(b0), "r"(b1));
}
__device__ __forceinline__ void ldsm4(uint32_t& r0, uint32_t& r1, uint32_t& r2,
                                      uint32_t& r3, uint32_t addr) {
    asm volatile("ldmatrix.sync.aligned.m8n8.x4.shared.b16 {%0,%1,%2,%3}, [%4];"
                 : "=r"(r0), "=r"(r1), "=r"(r2), "=r"(r3) : "r"(addr));
}
__device__ __forceinline__ void ldsm4t(uint32_t& r0, uint32_t& r1, uint32_t& r2,
                                       uint32_t& r3, uint32_t addr) {
    asm volatile("ldmatrix.sync.aligned.m8n8.x4.trans.shared.b16 {%0,%1,%2,%3}, [%4];"
                 : "=r"(r0), "=r"(r1), "=r"(r2), "=r"(r3) : "r"(addr));
}

// ---------------------------------------------------------------------------
// HMMA bf16-split GEMM — EXACT R10 version (fp32 epilogue only).
// ---------------------------------------------------------------------------
#define APITCH 40
#define BPITCH 136
#define A_PLANE (64*APITCH)
#define B_PLANE (32*BPITCH)
#define GBUF (2*A_PLANE + 2*B_PLANE)
#define GEMM_SMEM (2*GBUF*2)

__global__ __launch_bounds__(128) void mma_gemm_kernel(
    const __nv_bfloat16* __restrict__ Wh, const __nv_bfloat16* __restrict__ Wl,
    const __nv_bfloat16* __restrict__ Xh, const __nv_bfloat16* __restrict__ Xl,
    float* __restrict__ Y, const float* __restrict__ bias,
    int M, int K, long sX, long sY)
{
    extern __shared__ __nv_bfloat16 smd[];
    const uint32_t smem_base = (uint32_t)__cvta_generic_to_shared(smd);

    const int tid = threadIdx.x;
    const int wid = tid >> 5, lane = tid & 31;
    const int wm = wid & 1, wn = wid >> 1;
    const int g = lane >> 2, tg = lane & 3;
    const int mo = blockIdx.y * 64, no = blockIdx.x * 128;
    const __nv_bfloat16* Xhb = Xh + blockIdx.z * sX;
    const __nv_bfloat16* Xlb = Xl + blockIdx.z * sX;
    float* Yb = Y + blockIdx.z * sY;

    const int am = tid >> 1, ak = (tid & 1) * 16;
    const int bcol = (tid & 31) * 4;
    const int bk0 = (tid >> 5) * 2;

    float acc[2][8][4] = {};
    const int nch = K >> 5;

    uint4 awh[2], awl[2];
    uint2 bh[4][2], bl[4][2];

#define LOAD_REGS(kt)                                                            \
    {                                                                            \
        const __nv_bfloat16* Ah = Wh + (long)(mo + am) * K + (kt) + ak;          \
        const __nv_bfloat16* Al = Wl + (long)(mo + am) * K + (kt) + ak;          \
        awh[0] = *(const uint4*)Ah; awh[1] = *(const uint4*)(Ah + 8);            \
        awl[0] = *(const uint4*)Al; awl[1] = *(const uint4*)(Al + 8);            \
        _Pragma("unroll")                                                        \
        for (int I = 0; I < 4; I++) {                                            \
            int kr = (kt) + bk0 + 8 * I;                                         \
            const __nv_bfloat16* Bh = Xhb + (long)kr * 1024 + no + bcol;         \
            const __nv_bfloat16* Bl = Xlb + (long)kr * 1024 + no + bcol;         \
            bh[I][0] = *(const uint2*)Bh; bh[I][1] = *(const uint2*)(Bh + 1024); \
            bl[I][0] = *(const uint2*)Bl; bl[I][1] = *(const uint2*)(Bl + 1024); \
        }                                                                        \
    }

#define STORE_SMEM(buf)                                                          \
    {                                                                            \
        __nv_bfloat16* base = smd + (buf) * GBUF;                                \
        uint32_t* dH = (uint32_t*)(base + am * APITCH + ak);                     \
        uint32_t* dL = (uint32_t*)(base + A_PLANE + am * APITCH + ak);           \
        *(uint4*)dH = awh[0]; *(uint4*)(dH + 4) = awh[1];                        \
        *(uint4*)dL = awl[0]; *(uint4*)(dL + 4) = awl[1];                        \
        __nv_bfloat16* BH = base + 2 * A_PLANE;                                  \
        __nv_bfloat16* BL = base + 2 * A_PLANE + B_PLANE;                        \
        _Pragma("unroll")                                                        \
        for (int I = 0; I < 4; I++) {                                            \
            int kr = bk0 + 8 * I;                                                \
            *(uint2*)(BH + kr * BPITCH + bcol)       = bh[I][0];                 \
            *(uint2*)(BH + (kr + 1) * BPITCH + bcol) = bh[I][1];                 \
            *(uint2*)(BL + kr * BPITCH + bcol)       = bl[I][0];                 \
            *(uint2*)(BL + (kr + 1) * BPITCH + bcol) = bl[I][1];                 \
        }                                                                        \
    }

    LOAD_REGS(0);
    STORE_SMEM(0);
    if (nch > 1) LOAD_REGS(32);
    __syncthreads();

    const int a_row_l = lane & 15;
    const int a_khalf = (lane >> 4) * 8;
    const int b_krow  = (lane & 7) + 8 * ((lane >> 3) & 1);
    const int b_nhalf = (lane >> 4) * 8;

    for (int ch = 0; ch < nch; ch++) {
        if (ch + 1 < nch) STORE_SMEM((ch + 1) & 1);
        if (ch + 2 < nch) LOAD_REGS((ch + 2) * 32);

        uint32_t bufu = (uint32_t)((ch & 1) * GBUF) * 2u;
        uint32_t AH = smem_base + bufu;
        uint32_t ALo = AH + A_PLANE * 2;
        uint32_t BH = AH + 4 * A_PLANE;
        uint32_t BLo = BH + B_PLANE * 2;

#pragma unroll
        for (int k0 = 0; k0 < 32; k0 += 16) {
            uint32_t ah[2][4], al[2][4];
#pragma unroll
            for (int mt = 0; mt < 2; mt++) {
                int rowb = wm * 32 + mt * 16;
                uint32_t off = (uint32_t)((rowb + a_row_l) * APITCH + k0 + a_khalf) * 2u;
                ldsm4(ah[mt][0], ah[mt][1], ah[mt][2], ah[mt][3], AH + off);
                ldsm4(al[mt][0], al[mt][1], al[mt][2], al[mt][3], ALo + off);
            }
#pragma unroll
            for (int ntp = 0; ntp < 4; ntp++) {
                int nbase = wn * 64 + ntp * 16;
                uint32_t off = (uint32_t)((k0 + b_krow) * BPITCH + nbase + b_nhalf) * 2u;
                uint32_t bh0, bh1, bh2, bh3, bl0, bl1, bl2, bl3;
                ldsm4t(bh0, bh1, bh2, bh3, BH + off);
                ldsm4t(bl0, bl1, bl2, bl3, BLo + off);
#pragma unroll
                for (int mt = 0; mt < 2; mt++) {
                    float* d0 = acc[mt][ntp * 2];
                    float* d1 = acc[mt][ntp * 2 + 1];
                    mma16816(d0, ah[mt][0], ah[mt][1], ah[mt][2], ah[mt][3], bh0, bh1);
                    mma16816(d0, al[mt][0], al[mt][1], al[mt][2], al[mt][3], bh0, bh1);
                    mma16816(d0, ah[mt][0], ah[mt][1], ah[mt][2], ah[mt][3], bl0, bl1);
                    mma16816(d1, ah[mt][0], ah[mt][1], ah[mt][2], ah[mt][3], bh2, bh3);
                    mma16816(d1, al[mt][0], al[mt][1], al[mt][2], al[mt][3], bh2, bh3);
                    mma16816(d1, ah[mt][0], ah[mt][1], ah[mt][2], ah[mt][3], bl2, bl3);
                }
            }
        }
        if (ch + 1 < nch) __syncthreads();
    }

#pragma unroll
    for (int mt = 0; mt < 2; mt++) {
        int r0 = mo + wm * 32 + mt * 16 + g;
        int r1 = r0 + 8;
        float bv0 = bias ? bias[r0] : 0.f;
        float bv1 = bias ? bias[r1] : 0.f;
#pragma unroll
        for (int nt = 0; nt < 8; nt++) {
            int c = no + wn * 64 + nt * 8 + 2 * tg;
            float* d = acc[mt][nt];
            *(float2*)(Yb + (long)r0 * 1024 + c) = make_float2(d[0] + bv0, d[1] + bv0);
            *(float2*)(Yb + (long)r1 * 1024 + c) = make_float2(d[2] + bv1, d[3] + bv1);
        }
    }
#undef LOAD_REGS
#undef STORE_SMEM
}

// ---------------------------------------------------------------------------
// Fused BN: stats + apply + bf16 split (unchanged)
// ---------------------------------------------------------------------------
__global__ __launch_bounds__(256) void bn_fused_split(
    const float* __restrict__ X, __nv_bfloat16* __restrict__ H,
    __nv_bfloat16* __restrict__ L,
    const float* __restrict__ g, const float* __restrict__ be,
    long bsX, long bsP, int relu)
{
    int m = blockIdx.x, tid = threadIdx.x;
    float4 v[4];
    float s = 0.f, sq = 0.f;
#pragma unroll
    for (int b = 0; b < 4; b++) {
        v[b] = *(const float4*)(X + b * bsX + (long)m * 1024 + tid * 4);
        s  += v[b].x + v[b].y + v[b].z + v[b].w;
        sq += v[b].x*v[b].x + v[b].y*v[b].y + v[b].z*v[b].z + v[b].w*v[b].w;
    }
#pragma unroll
    for (int o = 16; o; o >>= 1) {
        s  += __shfl_xor_sync(0xffffffffu, s, o);
        sq += __shfl_xor_sync(0xffffffffu, sq, o);
    }
    __shared__ float ps[8], pq[8], bsc[1], bsh[1];
    if ((tid & 31) == 0) { ps[tid >> 5] = s; pq[tid >> 5] = sq; }
    __syncthreads();
    if (tid == 0) {
        s = 0.f; sq = 0.f;
#pragma unroll
        for (int i = 0; i < 8; i++) { s += ps[i]; sq += pq[i]; }
        float mean = s * (1.f / 4096.f);
        float var  = sq * (1.f / 4096.f) - mean * mean;
        float rstd = rsqrtf(var + 1e-5f);
        float sc = g[m] * rstd;
        bsc[0] = sc;
        bsh[0] = be[m] - mean * sc;
    }
    __syncthreads();
    float sc = bsc[0], sh = bsh[0];
#pragma unroll
    for (int b = 0; b < 4; b++) {
        float4 w = v[b];
        w.x = w.x * sc + sh; w.y = w.y * sc + sh;
        w.z = w.z * sc + sh; w.w = w.w * sc + sh;
        if (relu) {
            w.x = fmaxf(w.x, 0.f); w.y = fmaxf(w.y, 0.f);
            w.z = fmaxf(w.z, 0.f); w.w = fmaxf(w.w, 0.f);
        }
        __nv_bfloat16 h[4], l[4];
        splitf(w.x, h[0], l[0]); splitf(w.y, h[1], l[1]);
        splitf(w.z, h[2], l[2]); splitf(w.w, h[3], l[3]);
        long o = (long)b * bsP + (long)m * 1024 + tid * 4;
        *(uint2*)(H + o) = *(uint2*)h;
        *(uint2*)(L + o) = *(uint2*)l;
    }
}

__global__ __launch_bounds__(256) void bn_fused_out(
    const float* __restrict__ X, float* __restrict__ Y,
    const float* __restrict__ g, const float* __restrict__ be,
    long bsX, long bsY, int relu)
{
    int m = blockIdx.x, tid = threadIdx.x;
    float4 v[4];
    float s = 0.f, sq = 0.f;
#pragma unroll
    for (int b = 0; b < 4; b++) {
        v[b] = *(const float4*)(X + b * bsX + (long)m * 1024 + tid * 4);
        s  += v[b].x + v[b].y + v[b].z + v[b].w;
        sq += v[b].x*v[b].x + v[b].y*v[b].y + v[b].z*v[b].z + v[b].w*v[b].w;
    }
#pragma unroll
    for (int o = 16; o; o >>= 1) {
        s  += __shfl_xor_sync(0xffffffffu, s, o);
        sq += __shfl_xor_sync(0xffffffffu, sq, o);
    }
    __shared__ float ps[8], pq[8], bsc[1], bsh[1];
    if ((tid & 31) == 0) { ps[tid >> 5] = s; pq[tid >> 5] = sq; }
    __syncthreads();
    if (tid == 0) {
        s = 0.f; sq = 0.f;
#pragma unroll
        for (int i = 0; i < 8; i++) { s += ps[i]; sq += pq[i]; }
        float mean = s * (1.f / 4096.f);
        float var  = sq * (1.f / 4096.f) - mean * mean;
        float rstd = rsqrtf(var + 1e-5f);
        float sc = g[m] * rstd;
        bsc[0] = sc;
        bsh[0] = be[m] - mean * sc;
    }
    __syncthreads();
    float sc = bsc[0], sh = bsh[0];
#pragma unroll
    for (int b = 0; b < 4; b++) {
        float4 w = v[b];
        w.x = w.x * sc + sh; w.y = w.y * sc + sh;
        w.z = w.z * sc + sh; w.w = w.w * sc + sh;
        if (relu) {
            w.x = fmaxf(w.x, 0.f); w.y = fmaxf(w.y, 0.f);
            w.z = fmaxf(w.z, 0.f); w.w = fmaxf(w.w, 0.f);
        }
        *(float4*)(Y + (long)b * bsY + (long)m * 1024 + tid * 4) = w;
    }
}

// ---------------------------------------------------------------------------
// Tensor-core flash attention — pre-split bf16 plane inputs (R11, proven)
// ---------------------------------------------------------------------------
#define QP 24
#define KP 24
#define VP 136

__global__ __launch_bounds__(256) void attn_kernel(
    const __nv_bfloat16* __restrict__ Hp, const __nv_bfloat16* __restrict__ Lp,
    float* __restrict__ O) {
    __shared__ __nv_bfloat16 QH[32*QP], QL[32*QP];
    __shared__ __nv_bfloat16 KH[128*KP], KL[128*KP];
    __shared__ __nv_bfloat16 VH[16*VP], VL[16*VP];
    __shared__ float redmax[4][32], redsum[4][32];
    __shared__ float Of[4][2][16][17];
    __shared__ float rsinv[32];

    int b = blockIdx.z, head = blockIdx.y >> 2, t = blockIdx.y & 3;
    int r0 = blockIdx.x * 32;
    const __nv_bfloat16* Hb = Hp + (long)b * 768 * 1024;
    const __nv_bfloat16* Lb = Lp + (long)b * 768 * 1024;
    int tid = threadIdx.x, lane = tid & 31, wid = tid >> 5;
    int wm = wid & 1, wn = wid >> 1;
    int g = lane >> 2, tg = lane & 3;

    for (int i = tid; i < 512; i += 256) {
        int dd = i >> 5, q = i & 31;
        long off = (long)(head * 192 + dd * 4 + t) * 1024 + r0 + q;
        QH[q * QP + dd] = Hb[off];
        QL[q * QP + dd] = Lb[off];
    }
    __syncthreads();

    uint32_t qh[4], ql[4];
    {
        int r = wm * 16 + g;
        qh[0] = *(uint32_t*)&QH[r * QP + 2*tg];
        qh[1] = *(uint32_t*)&QH[(r + 8) * QP + 2*tg];
        qh[2] = *(uint32_t*)&QH[r * QP + 2*tg + 8];
        qh[3] = *(uint32_t*)&QH[(r + 8) * QP + 2*tg + 8];
        ql[0] = *(uint32_t*)&QL[r * QP + 2*tg];
        ql[1] = *(uint32_t*)&QL[(r + 8) * QP + 2*tg];
        ql[2] = *(uint32_t*)&QL[r * QP + 2*tg + 8];
        ql[3] = *(uint32_t*)&QL[(r + 8) * QP + 2*tg + 8];
    }

    float od[2][4] = {};
    float rm_lo = -1e30f, rm_hi = -1e30f, rs_lo = 0.f, rs_hi = 0.f;
    const float sc = 0.25f;
    const int rlo = wm * 16 + g, rhi = rlo + 8;

    for (int ch = 0; ch < 8; ch++) {
        __syncthreads();
        for (int i = tid; i < 2048; i += 256) {
            int dd = i >> 7, key = i & 127;
            long rk = (long)(head * 192 + 64 + dd * 4 + t) * 1024 + ch * 128 + key;
            KH[key * KP + dd] = Hb[rk];
            KL[key * KP + dd] = Lb[rk];
            long rv = (long)(head * 192 + 128 + dd * 4 + t) * 1024 + ch * 128 + key;
            VH[dd * VP + key] = Hb[rv];
            VL[dd * VP + key] = Lb[rv];
        }
        __syncthreads();

        float sacc[4][4] = {};
#pragma unroll
        for (int nt = 0; nt < 4; nt++) {
            int nb = wn * 32 + nt * 8 + g;
            uint32_t kb0 = *(uint32_t*)&KH[nb * KP + 2*tg];
            uint32_t kb1 = *(uint32_t*)&KH[nb * KP + 2*tg + 8];
            uint32_t kc0 = *(uint32_t*)&KL[nb * KP + 2*tg];
            uint32_t kc1 = *(uint32_t*)&KL[nb * KP + 2*tg + 8];
            mma16816(sacc[nt], qh[0], qh[1], qh[2], qh[3], kb0, kb1);
            mma16816(sacc[nt], ql[0], ql[1], ql[2], ql[3], kb0, kb1);
            mma16816(sacc[nt], qh[0], qh[1], qh[2], qh[3], kc0, kc1);
        }
        float mx_lo = -1e30f, mx_hi = -1e30f;
#pragma unroll
        for (int nt = 0; nt < 4; nt++) {
            sacc[nt][0] *= sc; sacc[nt][1] *= sc;
            sacc[nt][2] *= sc; sacc[nt][3] *= sc;
            mx_lo = fmaxf(mx_lo, fmaxf(sacc[nt][0], sacc[nt][1]));
            mx_hi = fmaxf(mx_hi, fmaxf(sacc[nt][2], sacc[nt][3]));
        }
        mx_lo = fmaxf(mx_lo, __shfl_xor_sync(0xffffffffu, mx_lo, 1));
        mx_lo = fmaxf(mx_lo, __shfl_xor_sync(0xffffffffu, mx_lo, 2));
        mx_hi = fmaxf(mx_hi, __shfl_xor_sync(0xffffffffu, mx_hi, 1));
        mx_hi = fmaxf(mx_hi, __shfl_xor_sync(0xffffffffu, mx_hi, 2));
        if (tg == 0) { redmax[wn][rlo] = mx_lo; redmax[wn][rhi] = mx_hi; }
        __syncthreads();

        float cm_lo = fmaxf(fmaxf(redmax[0][rlo], redmax[1][rlo]),
                            fmaxf(redmax[2][rlo], redmax[3][rlo]));
        float cm_hi = fmaxf(fmaxf(redmax[0][rhi], redmax[1][rhi]),
                            fmaxf(redmax[2][rhi], redmax[3][rhi]));
        float nm_lo = fmaxf(rm_lo, cm_lo), f_lo = __expf(rm_lo - nm_lo);
        float nm_hi = fmaxf(rm_hi, cm_hi), f_hi = __expf(rm_hi - nm_hi);
        rm_lo = nm_lo; rm_hi = nm_hi;

        float e[4][4];
        float sum_lo = 0.f, sum_hi = 0.f;
#pragma unroll
        for (int nt = 0; nt < 4; nt++) {
            e[nt][0] = __expf(sacc[nt][0] - nm_lo);
            e[nt][1] = __expf(sacc[nt][1] - nm_lo);
            e[nt][2] = __expf(sacc[nt][2] - nm_hi);
            e[nt][3] = __expf(sacc[nt][3] - nm_hi);
            sum_lo += e[nt][0] + e[nt][1];
            sum_hi += e[nt][2] + e[nt][3];
        }
        sum_lo += __shfl_xor_sync(0xffffffffu, sum_lo, 1);
        sum_lo += __shfl_xor_sync(0xffffffffu, sum_lo, 2);
        sum_hi += __shfl_xor_sync(0xffffffffu, sum_hi, 1);
        sum_hi += __shfl_xor_sync(0xffffffffu, sum_hi, 2);
        if (tg == 0) { redsum[wn][rlo] = sum_lo; redsum[wn][rhi] = sum_hi; }
        __syncthreads();

        rs_lo = rs_lo * f_lo + redsum[0][rlo] + redsum[1][rlo] + redsum[2][rlo] + redsum[3][rlo];
        rs_hi = rs_hi * f_hi + redsum[0][rhi] + redsum[1][rhi] + redsum[2][rhi] + redsum[3][rhi];

#pragma unroll
        for (int dn = 0; dn < 2; dn++) {
            od[dn][0] *= f_lo; od[dn][1] *= f_lo;
            od[dn][2] *= f_hi; od[dn][3] *= f_hi;
        }
        uint32_t ph[2][4], pl[2][4];
#pragma unroll
        for (int ks = 0; ks < 2; ks++) {
            pack2(e[2*ks][0],   e[2*ks][1],   ph[ks][0], pl[ks][0]);
            pack2(e[2*ks][2],   e[2*ks][3],   ph[ks][1], pl[ks][1]);
            pack2(e[2*ks+1][0], e[2*ks+1][1], ph[ks][2], pl[ks][2]);
            pack2(e[2*ks+1][2], e[2*ks+1][3], ph[ks][3], pl[ks][3]);
        }
#pragma unroll
        for (int ks = 0; ks < 2; ks++) {
#pragma unroll
            for (int dn = 0; dn < 2; dn++) {
                int vrow = dn * 8 + g;
                int kk = wn * 32 + ks * 16;
                uint32_t vb0 = *(uint32_t*)&VH[vrow * VP + kk + 2*tg];
                uint32_t vb1 = *(uint32_t*)&VH[vrow * VP + kk + 2*tg + 8];
                uint32_t vc0 = *(uint32_t*)&VL[vrow * VP + kk + 2*tg];
                uint32_t vc1 = *(uint32_t*)&VL[vrow * VP + kk + 2*tg + 8];
                mma16816(od[dn], ph[ks][0], ph[ks][1], ph[ks][2], ph[ks][3], vb0, vb1);
                mma16816(od[dn], pl[ks][0], pl[ks][1], pl[ks][2], pl[ks][3], vb0, vb1);
                mma16816(od[dn], ph[ks][0], ph[ks][1], ph[ks][2], ph[ks][3], vc0, vc1);
            }
        }
    }

#pragma unroll
    for (int dn = 0; dn < 2; dn++) {
        Of[wn][wm][g][dn*8 + 2*tg]       = od[dn][0];
        Of[wn][wm][g][dn*8 + 2*tg + 1]   = od[dn][1];
        Of[wn][wm][g+8][dn*8 + 2*tg]     = od[dn][2];
        Of[wn][wm][g+8][dn*8 + 2*tg + 1] = od[dn][3];
    }
    if (tg == 0 && wn == 0) {
        rsinv[rlo] = 1.f / rs_lo;
        rsinv[rhi] = 1.f / rs_hi;
    }
    __syncthreads();

    int q = tid & 31, dd = tid >> 5;
    float inv = rsinv[q];
    int qm = q >> 4, qr = q & 15;
    float* Ob = O + (long)b * 256 * 1024;
#pragma unroll
    for (int h2 = 0; h2 < 2; h2++) {
        int D = dd + h2 * 8;
        float v = (Of[0][qm][qr][D] + Of[1][qm][qr][D] +
                   Of[2][qm][qr][D] + Of[3][qm][qr][D]) * inv;
        Ob[(head * 64 + D * 4 + t) * 1024 + r0 + q] = v;
    }
}

// ---------------------------------------------------------------------------
// PE conv + residual; 4 pixels per thread (R11, proven). Split-plane output.
// ---------------------------------------------------------------------------
__global__ __launch_bounds__(256) void pe_kernel(
    const float* __restrict__ I, const float* __restrict__ pw,
    const float* __restrict__ pb,
    __nv_bfloat16* __restrict__ H, __nv_bfloat16* __restrict__ L, long bsP)
{
    int unit = blockIdx.x * 256 + threadIdx.x;
    int p4 = unit & 255;
    int m  = (unit >> 8) & 255;
    int b  = unit >> 16;
    int p  = p4 * 4;
    int h = p >> 5, w0 = p & 31;
    int co = m >> 2, t = m & 3, g = co >> 2;
    const float* Ib = I + (long)b * 256 * 1024;

    float4 res = *(const float4*)(Ib + m * 1024 + p);
    float acc[4] = {res.x + pb[m], res.y + pb[m], res.z + pb[m], res.w + pb[m]};

#pragma unroll
    for (int s = 0; s < 4; s++) {
        float sg = c_sgn[t * 4 + s];
        const float* wc = pw + ((long)c_cmp[t * 4 + s] * 64 + co) * 36;
        float part[4] = {0.f, 0.f, 0.f, 0.f};
#pragma unroll
        for (int cil = 0; cil < 4; cil++) {
            const float* in = Ib + ((g * 4 + cil) * 4 + s) * 1024;
            const float* wk = wc + cil * 9;
#pragma unroll
            for (int kh = 0; kh < 3; kh++) {
                int hh = h + kh - 1;
                if (hh < 0 || hh > 31) continue;
                const float* row = in + hh * 32;
                float v[6];
                v[0] = (w0 - 1 >= 0) ? row[w0 - 1] : 0.f;
                v[1] = row[w0];
                v[2] = row[w0 + 1];
                v[3] = row[w0 + 2];
                v[4] = row[w0 + 3];
                v[5] = (w0 + 4 <= 31) ? row[w0 + 4] : 0.f;
                float wk0 = wk[kh * 3], wk1 = wk[kh * 3 + 1], wk2 = wk[kh * 3 + 2];
#pragma unroll
                for (int j = 0; j < 4; j++)
                    part[j] += v[j] * wk0 + v[j + 1] * wk1 + v[j + 2] * wk2;
            }
        }
#pragma unroll
        for (int j = 0; j < 4; j++) acc[j] += sg * part[j];
    }

    __nv_bfloat16 hh4[4], ll4[4];
#pragma unroll
    for (int j = 0; j < 4; j++) splitf(acc[j], hh4[j], ll4[j]);
    long o = (long)b * bsP + (long)m * 1024 + p;
    *(uint2*)(H + o) = *(uint2*)hh4;
    *(uint2*)(L + o) = *(uint2*)ll4;
}

// ---------------------------------------------------------------------------
extern "C" void kernel_launch(void* const* d_in, const int* in_sizes, int n_in,
                              void* d_out, int out_size) {
    const float* x      = (const float*)d_in[0];
    const float* cv1_w  = (const float*)d_in[1];
    const float* bn1_g  = (const float*)d_in[2];
    const float* bn1_b  = (const float*)d_in[3];
    const float* qkv_w  = (const float*)d_in[4];
    const float* qkv_b  = (const float*)d_in[5];
    const float* proj_w = (const float*)d_in[6];
    const float* proj_b = (const float*)d_in[7];
    const float* pe_w   = (const float*)d_in[8];
    const float* pe_b   = (const float*)d_in[9];
    const float* ang    = (const float*)d_in[10];
    const float* anb    = (const float*)d_in[11];
    const float* f1w    = (const float*)d_in[12];
    const float* f1g    = (const float*)d_in[13];
    const float* f1b    = (const float*)d_in[14];
    const float* f2w    = (const float*)d_in[15];
    const float* f2g    = (const float*)d_in[16];
    const float* f2b    = (const float*)d_in[17];
    const float* cv2_w  = (const float*)d_in[18];
    const float* bn2_g  = (const float*)d_in[19];
    const float* bn2_b  = (const float*)d_in[20];

    float *buf1, *buf2, *buf3;
    __nv_bfloat16 *xh0, *xl0, *xh1, *xl1, *qh, *ql, *Wh, *Wl;
    cudaGetSymbolAddress((void**)&buf1, g_buf1);
    cudaGetSymbolAddress((void**)&buf2, g_buf2);
    cudaGetSymbolAddress((void**)&buf3, g_buf3);
    cudaGetSymbolAddress((void**)&xh0,  g_xh0);
    cudaGetSymbolAddress((void**)&xl0,  g_xl0);
    cudaGetSymbolAddress((void**)&xh1,  g_xh1);
    cudaGetSymbolAddress((void**)&xl1,  g_xl1);
    cudaGetSymbolAddress((void**)&qh,   g_qh);
    cudaGetSymbolAddress((void**)&ql,   g_ql);
    cudaGetSymbolAddress((void**)&Wh,   g_Wh);
    cudaGetSymbolAddress((void**)&Wl,   g_Wl);

    const long S512 = 512L * 1024, S768 = 768L * 1024, S256 = 256L * 1024;

    cudaFuncSetAttribute(mma_gemm_kernel,
                         cudaFuncAttributeMaxDynamicSharedMemorySize, GEMM_SMEM);

    expand_all_kernel<<<dim3(32, 6), 256>>>(cv1_w, qkv_w, proj_w, f1w, f2w, cv2_w, Wh, Wl);
    split_x_kernel<<<2048, 256>>>(x, xh0, xl0);

    // cv1 + iqbn(+relu) -> P1 (512 rows)
    mma_gemm_kernel<<<dim3(8, 8, 4), 128, GEMM_SMEM>>>(Wh + OFF_W1, Wl + OFF_W1, xh0, xl0,
                                                        buf1, nullptr, 512, 512, S512, S512);
    bn_fused_split<<<512, 256>>>(buf1, xh1, xl1, bn1_g, bn1_b, S512, S512, 1);

    // qkv (fp32 + bias) then split ONCE into planes
    mma_gemm_kernel<<<dim3(8, 12, 4), 128, GEMM_SMEM>>>(Wh + OFF_WQ, Wl + OFF_WQ, xh1, xl1,
                                                         buf2, qkv_b, 768, 256, S512, S768);
    split_x_kernel<<<3072, 256>>>(buf2, qh, ql);

    // attention (tensor cores, pre-split inputs)
    attn_kernel<<<dim3(32, 16, 4), 256>>>(qh, ql, buf3);

    // pe conv + residual -> P0 (4 px/thread)
    pe_kernel<<<1024, 256>>>(buf3, pe_w, pe_b, xh0, xl0, S512);

    // proj + attn_norm -> P0
    mma_gemm_kernel<<<dim3(8, 4, 4), 128, GEMM_SMEM>>>(Wh + OFF_WP, Wl + OFF_WP, xh0, xl0,
                                                        buf3, proj_b, 256, 256, S512, S256);
    bn_fused_split<<<256, 256>>>(buf3, xh0, xl0, ang, anb, S256, S512, 0);

    // ffn1 + bn(+relu) -> P0
    mma_gemm_kernel<<<dim3(8, 8, 4), 128, GEMM_SMEM>>>(Wh + OFF_F1, Wl + OFF_F1, xh0, xl0,
                                                        buf2, nullptr, 512, 256, S512, S512);
    bn_fused_split<<<512, 256>>>(buf2, xh0, xl0, f1g, f1b, S512, S512, 1);

    // ffn2 + bn -> P1 rows 0..255 (rows 256..511 = b from bn1)
    mma_gemm_kernel<<<dim3(8, 4, 4), 128, GEMM_SMEM>>>(Wh + OFF_F2, Wl + OFF_F2, xh0, xl0,
                                                        buf3, nullptr, 256, 512, S512, S256);
    bn_fused_split<<<256, 256>>>(buf3, xh1, xl1, f2g, f2b, S256, S512, 0);

    // cv2 on concat + bn + relu -> d_out
    mma_gemm_kernel<<<dim3(8, 8, 4), 128, GEMM_SMEM>>>(Wh + OFF_C2, Wl + OFF_C2, xh1, xl1,
                                                        buf2, nullptr, 512, 512, S512, S512);
    bn_fused_out<<<512, 256>>>(buf2, (float*)d_out, bn2_g, bn2_b, S512, S512, 1);
}

// round 13
// speedup vs baseline: 1.9238x; 1.6942x over previous
#include <cuda_runtime.h>
#include <cuda_bf16.h>
#include <cstdint>

// ---------------------------------------------------------------------------
// Quaternion Hamilton-product tables
// ---------------------------------------------------------------------------
__constant__ int   c_cmp[16] = {0,1,2,3,  1,0,3,2,  2,3,0,1,  3,2,1,0};
__constant__ float c_sgn[16] = {1.f,-1.f,-1.f,-1.f,
                                1.f, 1.f, 1.f,-1.f,
                                1.f,-1.f, 1.f, 1.f,
                                1.f, 1.f,-1.f, 1.f};

// ---------------------------------------------------------------------------
// Scratch (device globals)
// ---------------------------------------------------------------------------
__device__ float g_buf1[4*512*1024];
__device__ float g_buf2[4*768*1024];
__device__ float g_buf3[4*256*1024];
__device__ __align__(16) __nv_bfloat16 g_xh0[4*512*1024];
__device__ __align__(16) __nv_bfloat16 g_xl0[4*512*1024];
__device__ __align__(16) __nv_bfloat16 g_xh1[4*512*1024];
__device__ __align__(16) __nv_bfloat16 g_xl1[4*512*1024];
__device__ __align__(16) __nv_bfloat16 g_Wh[1048576];
__device__ __align__(16) __nv_bfloat16 g_Wl[1048576];

#define OFF_W1 0
#define OFF_WQ (OFF_W1 + 512*512)
#define OFF_WP (OFF_WQ + 768*256)
#define OFF_F1 (OFF_WP + 256*256)
#define OFF_F2 (OFF_F1 + 512*256)
#define OFF_C2 (OFF_F2 + 256*512)

__device__ __forceinline__ void splitf(float v, __nv_bfloat16& h, __nv_bfloat16& l) {
    h = __float2bfloat16(v);
    l = __float2bfloat16(v - __bfloat162float(h));
}
__device__ __forceinline__ void pack2(float x, float y, uint32_t& h, uint32_t& l) {
    __nv_bfloat16 hx, lx, hy, ly;
    splitf(x, hx, lx); splitf(y, hy, ly);
    h = (uint32_t)*(unsigned short*)&hx | ((uint32_t)*(unsigned short*)&hy << 16);
    l = (uint32_t)*(unsigned short*)&lx | ((uint32_t)*(unsigned short*)&ly << 16);
}

// ---------------------------------------------------------------------------
// Fused expansion: quaternion weights -> dense bf16 hi/lo GEMM weights
// ---------------------------------------------------------------------------
__global__ void expand_all_kernel(const float* __restrict__ w0, const float* __restrict__ w1,
                                  const float* __restrict__ w2, const float* __restrict__ w3,
                                  const float* __restrict__ w4, const float* __restrict__ w5,
                                  __nv_bfloat16* __restrict__ Wh, __nv_bfloat16* __restrict__ Wl) {
    const int Couts[6] = {128,192,64,128,64,128};
    const int Cins [6] = {128, 64,64, 64,128,128};
    const int offs [6] = {OFF_W1,OFF_WQ,OFF_WP,OFF_F1,OFF_F2,OFF_C2};
    const float* srcs[6] = {w0,w1,w2,w3,w4,w5};
    int q = blockIdx.y;
    int Cout = Couts[q], Cin = Cins[q];
    const float* w = srcs[q];
    int off = offs[q];
    int total = 16 * Cout * Cin;
    for (int i = blockIdx.x * blockDim.x + threadIdx.x; i < total;
         i += gridDim.x * blockDim.x) {
        int s = i & 3, t = (i >> 2) & 3;
        int rest = i >> 4;
        int ci = rest % Cin, co = rest / Cin;
        float val = c_sgn[t*4 + s] * w[c_cmp[t*4 + s] * Cout * Cin + co * Cin + ci];
        __nv_bfloat16 h, l;
        splitf(val, h, l);
        int idx = off + (co*4 + t) * (4*Cin) + ci*4 + s;
        Wh[idx] = h;
        Wl[idx] = l;
    }
}

// ---------------------------------------------------------------------------
// Plain fp32 -> bf16 hi/lo split (network input x)
// ---------------------------------------------------------------------------
__global__ __launch_bounds__(256) void split_x_kernel(const float* __restrict__ X,
                                                      __nv_bfloat16* __restrict__ H,
                                                      __nv_bfloat16* __restrict__ L) {
    int i = blockIdx.x * 256 + threadIdx.x;
    float4 v = ((const float4*)X)[i];
    __nv_bfloat16 h[4], l[4];
    splitf(v.x, h[0], l[0]); splitf(v.y, h[1], l[1]);
    splitf(v.z, h[2], l[2]); splitf(v.w, h[3], l[3]);
    *(uint2*)(H + (long)i * 4) = *(uint2*)h;
    *(uint2*)(L + (long)i * 4) = *(uint2*)l;
}

// ---------------------------------------------------------------------------
// mma / ldmatrix helpers
// ---------------------------------------------------------------------------
__device__ __forceinline__ void mma16816(float* d, uint32_t a0, uint32_t a1,
                                         uint32_t a2, uint32_t a3,
                                         uint32_t b0, uint32_t b1) {
    asm volatile(
        "mma.sync.aligned.m16n8k16.row.col.f32.bf16.bf16.f32 "
        "{%0,%1,%2,%3}, {%4,%5,%6,%7}, {%8,%9}, {%0,%1,%2,%3};"
        : "+f"(d[0]), "+f"(d[1]), "+f"(d[2]), "+f"(d[3])
        : "r"(a0), "r"(a1), "r"(a2), "r"(a3), "r"(b0), "r"(b1));
}
__device__ __forceinline__ void ldsm4(uint32_t& r0, uint32_t& r1, uint32_t& r2,
                                      uint32_t& r3, uint32_t addr) {
    asm volatile("ldmatrix.sync.aligned.m8n8.x4.shared.b16 {%0,%1,%2,%3}, [%4];"
                 : "=r"(r0), "=r"(r1), "=r"(r2), "=r"(r3) : "r"(addr));
}
__device__ __forceinline__ void ldsm4t(uint32_t& r0, uint32_t& r1, uint32_t& r2,
                                       uint32_t& r3, uint32_t addr) {
    asm volatile("ldmatrix.sync.aligned.m8n8.x4.trans.shared.b16 {%0,%1,%2,%3}, [%4];"
                 : "=r"(r0), "=r"(r1), "=r"(r2), "=r"(r3) : "r"(addr));
}

// ---------------------------------------------------------------------------
// HMMA bf16-split GEMM. CTA tile 64m x 128n, 4 warps (warp tile 32x64),
// K-chunk 32, double-buffered dynamic smem. (exact R10)
// ---------------------------------------------------------------------------
#define APITCH 40
#define BPITCH 136
#define A_PLANE (64*APITCH)
#define B_PLANE (32*BPITCH)
#define GBUF (2*A_PLANE + 2*B_PLANE)
#define GEMM_SMEM (2*GBUF*2)

__global__ __launch_bounds__(128) void mma_gemm_kernel(
    const __nv_bfloat16* __restrict__ Wh, const __nv_bfloat16* __restrict__ Wl,
    const __nv_bfloat16* __restrict__ Xh, const __nv_bfloat16* __restrict__ Xl,
    float* __restrict__ Y, const float* __restrict__ bias,
    int M, int K, long sX, long sY)
{
    extern __shared__ __nv_bfloat16 smd[];
    const uint32_t smem_base = (uint32_t)__cvta_generic_to_shared(smd);

    const int tid = threadIdx.x;
    const int wid = tid >> 5, lane = tid & 31;
    const int wm = wid & 1, wn = wid >> 1;
    const int g = lane >> 2, tg = lane & 3;
    const int mo = blockIdx.y * 64, no = blockIdx.x * 128;
    const __nv_bfloat16* Xhb = Xh + blockIdx.z * sX;
    const __nv_bfloat16* Xlb = Xl + blockIdx.z * sX;
    float* Yb = Y + blockIdx.z * sY;

    const int am = tid >> 1, ak = (tid & 1) * 16;
    const int bcol = (tid & 31) * 4;
    const int bk0 = (tid >> 5) * 2;

    float acc[2][8][4] = {};
    const int nch = K >> 5;

    uint4 awh[2], awl[2];
    uint2 bh[4][2], bl[4][2];

#define LOAD_REGS(kt)                                                            \
    {                                                                            \
        const __nv_bfloat16* Ah = Wh + (long)(mo + am) * K + (kt) + ak;          \
        const __nv_bfloat16* Al = Wl + (long)(mo + am) * K + (kt) + ak;          \
        awh[0] = *(const uint4*)Ah; awh[1] = *(const uint4*)(Ah + 8);            \
        awl[0] = *(const uint4*)Al; awl[1] = *(const uint4*)(Al + 8);            \
        _Pragma("unroll")                                                        \
        for (int I = 0; I < 4; I++) {                                            \
            int kr = (kt) + bk0 + 8 * I;                                         \
            const __nv_bfloat16* Bh = Xhb + (long)kr * 1024 + no + bcol;         \
            const __nv_bfloat16* Bl = Xlb + (long)kr * 1024 + no + bcol;         \
            bh[I][0] = *(const uint2*)Bh; bh[I][1] = *(const uint2*)(Bh + 1024); \
            bl[I][0] = *(const uint2*)Bl; bl[I][1] = *(const uint2*)(Bl + 1024); \
        }                                                                        \
    }

#define STORE_SMEM(buf)                                                          \
    {                                                                            \
        __nv_bfloat16* base = smd + (buf) * GBUF;                                \
        uint32_t* dH = (uint32_t*)(base + am * APITCH + ak);                     \
        uint32_t* dL = (uint32_t*)(base + A_PLANE + am * APITCH + ak);           \
        *(uint4*)dH = awh[0]; *(uint4*)(dH + 4) = awh[1];                        \
        *(uint4*)dL = awl[0]; *(uint4*)(dL + 4) = awl[1];                        \
        __nv_bfloat16* BH = base + 2 * A_PLANE;                                  \
        __nv_bfloat16* BL = base + 2 * A_PLANE + B_PLANE;                        \
        _Pragma("unroll")                                                        \
        for (int I = 0; I < 4; I++) {                                            \
            int kr = bk0 + 8 * I;                                                \
            *(uint2*)(BH + kr * BPITCH + bcol)       = bh[I][0];                 \
            *(uint2*)(BH + (kr + 1) * BPITCH + bcol) = bh[I][1];                 \
            *(uint2*)(BL + kr * BPITCH + bcol)       = bl[I][0];                 \
            *(uint2*)(BL + (kr + 1) * BPITCH + bcol) = bl[I][1];                 \
        }                                                                        \
    }

    LOAD_REGS(0);
    STORE_SMEM(0);
    if (nch > 1) LOAD_REGS(32);
    __syncthreads();

    const int a_row_l = lane & 15;
    const int a_khalf = (lane >> 4) * 8;
    const int b_krow  = (lane & 7) + 8 * ((lane >> 3) & 1);
    const int b_nhalf = (lane >> 4) * 8;

    for (int ch = 0; ch < nch; ch++) {
        if (ch + 1 < nch) STORE_SMEM((ch + 1) & 1);
        if (ch + 2 < nch) LOAD_REGS((ch + 2) * 32);

        uint32_t bufu = (uint32_t)((ch & 1) * GBUF) * 2u;
        uint32_t AH = smem_base + bufu;
        uint32_t ALo = AH + A_PLANE * 2;
        uint32_t BH = AH + 4 * A_PLANE;
        uint32_t BLo = BH + B_PLANE * 2;

#pragma unroll
        for (int k0 = 0; k0 < 32; k0 += 16) {
            uint32_t ah[2][4], al[2][4];
#pragma unroll
            for (int mt = 0; mt < 2; mt++) {
                int rowb = wm * 32 + mt * 16;
                uint32_t off = (uint32_t)((rowb + a_row_l) * APITCH + k0 + a_khalf) * 2u;
                ldsm4(ah[mt][0], ah[mt][1], ah[mt][2], ah[mt][3], AH + off);
                ldsm4(al[mt][0], al[mt][1], al[mt][2], al[mt][3], ALo + off);
            }
#pragma unroll
            for (int ntp = 0; ntp < 4; ntp++) {
                int nbase = wn * 64 + ntp * 16;
                uint32_t off = (uint32_t)((k0 + b_krow) * BPITCH + nbase + b_nhalf) * 2u;
                uint32_t bh0, bh1, bh2, bh3, bl0, bl1, bl2, bl3;
                ldsm4t(bh0, bh1, bh2, bh3, BH + off);
                ldsm4t(bl0, bl1, bl2, bl3, BLo + off);
#pragma unroll
                for (int mt = 0; mt < 2; mt++) {
                    float* d0 = acc[mt][ntp * 2];
                    float* d1 = acc[mt][ntp * 2 + 1];
                    mma16816(d0, ah[mt][0], ah[mt][1], ah[mt][2], ah[mt][3], bh0, bh1);
                    mma16816(d0, al[mt][0], al[mt][1], al[mt][2], al[mt][3], bh0, bh1);
                    mma16816(d0, ah[mt][0], ah[mt][1], ah[mt][2], ah[mt][3], bl0, bl1);
                    mma16816(d1, ah[mt][0], ah[mt][1], ah[mt][2], ah[mt][3], bh2, bh3);
                    mma16816(d1, al[mt][0], al[mt][1], al[mt][2], al[mt][3], bh2, bh3);
                    mma16816(d1, ah[mt][0], ah[mt][1], ah[mt][2], ah[mt][3], bl2, bl3);
                }
            }
        }
        if (ch + 1 < nch) __syncthreads();
    }

#pragma unroll
    for (int mt = 0; mt < 2; mt++) {
        int r0 = mo + wm * 32 + mt * 16 + g;
        int r1 = r0 + 8;
        float bv0 = bias ? bias[r0] : 0.f;
        float bv1 = bias ? bias[r1] : 0.f;
#pragma unroll
        for (int nt = 0; nt < 8; nt++) {
            int c = no + wn * 64 + nt * 8 + 2 * tg;
            float* d = acc[mt][nt];
            *(float2*)(Yb + (long)r0 * 1024 + c) = make_float2(d[0] + bv0, d[1] + bv0);
            *(float2*)(Yb + (long)r1 * 1024 + c) = make_float2(d[2] + bv1, d[3] + bv1);
        }
    }
#undef LOAD_REGS
#undef STORE_SMEM
}

// ---------------------------------------------------------------------------
// Fused BN: stats + apply + bf16 split (exact R10)
// ---------------------------------------------------------------------------
__global__ __launch_bounds__(256) void bn_fused_split(
    const float* __restrict__ X, __nv_bfloat16* __restrict__ H,
    __nv_bfloat16* __restrict__ L,
    const float* __restrict__ g, const float* __restrict__ be,
    long bsX, long bsP, int relu)
{
    int m = blockIdx.x, tid = threadIdx.x;
    float4 v[4];
    float s = 0.f, sq = 0.f;
#pragma unroll
    for (int b = 0; b < 4; b++) {
        v[b] = *(const float4*)(X + b * bsX + (long)m * 1024 + tid * 4);
        s  += v[b].x + v[b].y + v[b].z + v[b].w;
        sq += v[b].x*v[b].x + v[b].y*v[b].y + v[b].z*v[b].z + v[b].w*v[b].w;
    }
#pragma unroll
    for (int o = 16; o; o >>= 1) {
        s  += __shfl_xor_sync(0xffffffffu, s, o);
        sq += __shfl_xor_sync(0xffffffffu, sq, o);
    }
    __shared__ float ps[8], pq[8], bsc[1], bsh[1];
    if ((tid & 31) == 0) { ps[tid >> 5] = s; pq[tid >> 5] = sq; }
    __syncthreads();
    if (tid == 0) {
        s = 0.f; sq = 0.f;
#pragma unroll
        for (int i = 0; i < 8; i++) { s += ps[i]; sq += pq[i]; }
        float mean = s * (1.f / 4096.f);
        float var  = sq * (1.f / 4096.f) - mean * mean;
        float rstd = rsqrtf(var + 1e-5f);
        float sc = g[m] * rstd;
        bsc[0] = sc;
        bsh[0] = be[m] - mean * sc;
    }
    __syncthreads();
    float sc = bsc[0], sh = bsh[0];
#pragma unroll
    for (int b = 0; b < 4; b++) {
        float4 w = v[b];
        w.x = w.x * sc + sh; w.y = w.y * sc + sh;
        w.z = w.z * sc + sh; w.w = w.w * sc + sh;
        if (relu) {
            w.x = fmaxf(w.x, 0.f); w.y = fmaxf(w.y, 0.f);
            w.z = fmaxf(w.z, 0.f); w.w = fmaxf(w.w, 0.f);
        }
        __nv_bfloat16 h[4], l[4];
        splitf(w.x, h[0], l[0]); splitf(w.y, h[1], l[1]);
        splitf(w.z, h[2], l[2]); splitf(w.w, h[3], l[3]);
        long o = (long)b * bsP + (long)m * 1024 + tid * 4;
        *(uint2*)(H + o) = *(uint2*)h;
        *(uint2*)(L + o) = *(uint2*)l;
    }
}

__global__ __launch_bounds__(256) void bn_fused_out(
    const float* __restrict__ X, float* __restrict__ Y,
    const float* __restrict__ g, const float* __restrict__ be,
    long bsX, long bsY, int relu)
{
    int m = blockIdx.x, tid = threadIdx.x;
    float4 v[4];
    float s = 0.f, sq = 0.f;
#pragma unroll
    for (int b = 0; b < 4; b++) {
        v[b] = *(const float4*)(X + b * bsX + (long)m * 1024 + tid * 4);
        s  += v[b].x + v[b].y + v[b].z + v[b].w;
        sq += v[b].x*v[b].x + v[b].y*v[b].y + v[b].z*v[b].z + v[b].w*v[b].w;
    }
#pragma unroll
    for (int o = 16; o; o >>= 1) {
        s  += __shfl_xor_sync(0xffffffffu, s, o);
        sq += __shfl_xor_sync(0xffffffffu, sq, o);
    }
    __shared__ float ps[8], pq[8], bsc[1], bsh[1];
    if ((tid & 31) == 0) { ps[tid >> 5] = s; pq[tid >> 5] = sq; }
    __syncthreads();
    if (tid == 0) {
        s = 0.f; sq = 0.f;
#pragma unroll
        for (int i = 0; i < 8; i++) { s += ps[i]; sq += pq[i]; }
        float mean = s * (1.f / 4096.f);
        float var  = sq * (1.f / 4096.f) - mean * mean;
        float rstd = rsqrtf(var + 1e-5f);
        float sc = g[m] * rstd;
        bsc[0] = sc;
        bsh[0] = be[m] - mean * sc;
    }
    __syncthreads();
    float sc = bsc[0], sh = bsh[0];
#pragma unroll
    for (int b = 0; b < 4; b++) {
        float4 w = v[b];
        w.x = w.x * sc + sh; w.y = w.y * sc + sh;
        w.z = w.z * sc + sh; w.w = w.w * sc + sh;
        if (relu) {
            w.x = fmaxf(w.x, 0.f); w.y = fmaxf(w.y, 0.f);
            w.z = fmaxf(w.z, 0.f); w.w = fmaxf(w.w, 0.f);
        }
        *(float4*)(Y + (long)b * bsY + (long)m * 1024 + tid * 4) = w;
    }
}

// ---------------------------------------------------------------------------
// Tensor-core flash attention (exact R10: fp32 input, in-kernel split)
// ---------------------------------------------------------------------------
#define QP 24
#define KP 24
#define VP 136

__global__ __launch_bounds__(256) void attn_kernel(const float* __restrict__ Yq,
                                                   float* __restrict__ O) {
    __shared__ __nv_bfloat16 QH[32*QP], QL[32*QP];
    __shared__ __nv_bfloat16 KH[128*KP], KL[128*KP];
    __shared__ __nv_bfloat16 VH[16*VP], VL[16*VP];
    __shared__ float redmax[4][32], redsum[4][32];
    __shared__ float Of[4][2][16][17];
    __shared__ float rsinv[32];

    int b = blockIdx.z, head = blockIdx.y >> 2, t = blockIdx.y & 3;
    int r0 = blockIdx.x * 32;
    const float* Yb = Yq + (long)b * 768 * 1024;
    int tid = threadIdx.x, lane = tid & 31, wid = tid >> 5;
    int wm = wid & 1, wn = wid >> 1;
    int g = lane >> 2, tg = lane & 3;

    for (int i = tid; i < 512; i += 256) {
        int dd = i >> 5, q = i & 31;
        float v = Yb[(head * 192 + dd * 4 + t) * 1024 + r0 + q];
        __nv_bfloat16 h, l; splitf(v, h, l);
        QH[q * QP + dd] = h;
        QL[q * QP + dd] = l;
    }
    __syncthreads();

    uint32_t qh[4], ql[4];
    {
        int r = wm * 16 + g;
        qh[0] = *(uint32_t*)&QH[r * QP + 2*tg];
        qh[1] = *(uint32_t*)&QH[(r + 8) * QP + 2*tg];
        qh[2] = *(uint32_t*)&QH[r * QP + 2*tg + 8];
        qh[3] = *(uint32_t*)&QH[(r + 8) * QP + 2*tg + 8];
        ql[0] = *(uint32_t*)&QL[r * QP + 2*tg];
        ql[1] = *(uint32_t*)&QL[(r + 8) * QP + 2*tg];
        ql[2] = *(uint32_t*)&QL[r * QP + 2*tg + 8];
        ql[3] = *(uint32_t*)&QL[(r + 8) * QP + 2*tg + 8];
    }

    float od[2][4] = {};
    float rm_lo = -1e30f, rm_hi = -1e30f, rs_lo = 0.f, rs_hi = 0.f;
    const float sc = 0.25f;
    const int rlo = wm * 16 + g, rhi = rlo + 8;

    for (int ch = 0; ch < 8; ch++) {
        __syncthreads();
        for (int i = tid; i < 2048; i += 256) {
            int dd = i >> 7, key = i & 127;
            float kval = Yb[(head * 192 + 64 + dd * 4 + t) * 1024 + ch * 128 + key];
            __nv_bfloat16 h, l; splitf(kval, h, l);
            KH[key * KP + dd] = h; KL[key * KP + dd] = l;
            float vval = Yb[(head * 192 + 128 + dd * 4 + t) * 1024 + ch * 128 + key];
            splitf(vval, h, l);
            VH[dd * VP + key] = h; VL[dd * VP + key] = l;
        }
        __syncthreads();

        float sacc[4][4] = {};
#pragma unroll
        for (int nt = 0; nt < 4; nt++) {
            int nb = wn * 32 + nt * 8 + g;
            uint32_t kb0 = *(uint32_t*)&KH[nb * KP + 2*tg];
            uint32_t kb1 = *(uint32_t*)&KH[nb * KP + 2*tg + 8];
            uint32_t kc0 = *(uint32_t*)&KL[nb * KP + 2*tg];
            uint32_t kc1 = *(uint32_t*)&KL[nb * KP + 2*tg + 8];
            mma16816(sacc[nt], qh[0], qh[1], qh[2], qh[3], kb0, kb1);
            mma16816(sacc[nt], ql[0], ql[1], ql[2], ql[3], kb0, kb1);
            mma16816(sacc[nt], qh[0], qh[1], qh[2], qh[3], kc0, kc1);
        }
        float mx_lo = -1e30f, mx_hi = -1e30f;
#pragma unroll
        for (int nt = 0; nt < 4; nt++) {
            sacc[nt][0] *= sc; sacc[nt][1] *= sc;
            sacc[nt][2] *= sc; sacc[nt][3] *= sc;
            mx_lo = fmaxf(mx_lo, fmaxf(sacc[nt][0], sacc[nt][1]));
            mx_hi = fmaxf(mx_hi, fmaxf(sacc[nt][2], sacc[nt][3]));
        }
        mx_lo = fmaxf(mx_lo, __shfl_xor_sync(0xffffffffu, mx_lo, 1));
        mx_lo = fmaxf(mx_lo, __shfl_xor_sync(0xffffffffu, mx_lo, 2));
        mx_hi = fmaxf(mx_hi, __shfl_xor_sync(0xffffffffu, mx_hi, 1));
        mx_hi = fmaxf(mx_hi, __shfl_xor_sync(0xffffffffu, mx_hi, 2));
        if (tg == 0) { redmax[wn][rlo] = mx_lo; redmax[wn][rhi] = mx_hi; }
        __syncthreads();

        float cm_lo = fmaxf(fmaxf(redmax[0][rlo], redmax[1][rlo]),
                            fmaxf(redmax[2][rlo], redmax[3][rlo]));
        float cm_hi = fmaxf(fmaxf(redmax[0][rhi], redmax[1][rhi]),
                            fmaxf(redmax[2][rhi], redmax[3][rhi]));
        float nm_lo = fmaxf(rm_lo, cm_lo), f_lo = __expf(rm_lo - nm_lo);
        float nm_hi = fmaxf(rm_hi, cm_hi), f_hi = __expf(rm_hi - nm_hi);
        rm_lo = nm_lo; rm_hi = nm_hi;

        float e[4][4];
        float sum_lo = 0.f, sum_hi = 0.f;
#pragma unroll
        for (int nt = 0; nt < 4; nt++) {
            e[nt][0] = __expf(sacc[nt][0] - nm_lo);
            e[nt][1] = __expf(sacc[nt][1] - nm_lo);
            e[nt][2] = __expf(sacc[nt][2] - nm_hi);
            e[nt][3] = __expf(sacc[nt][3] - nm_hi);
            sum_lo += e[nt][0] + e[nt][1];
            sum_hi += e[nt][2] + e[nt][3];
        }
        sum_lo += __shfl_xor_sync(0xffffffffu, sum_lo, 1);
        sum_lo += __shfl_xor_sync(0xffffffffu, sum_lo, 2);
        sum_hi += __shfl_xor_sync(0xffffffffu, sum_hi, 1);
        sum_hi += __shfl_xor_sync(0xffffffffu, sum_hi, 2);
        if (tg == 0) { redsum[wn][rlo] = sum_lo; redsum[wn][rhi] = sum_hi; }
        __syncthreads();

        rs_lo = rs_lo * f_lo + redsum[0][rlo] + redsum[1][rlo] + redsum[2][rlo] + redsum[3][rlo];
        rs_hi = rs_hi * f_hi + redsum[0][rhi] + redsum[1][rhi] + redsum[2][rhi] + redsum[3][rhi];

#pragma unroll
        for (int dn = 0; dn < 2; dn++) {
            od[dn][0] *= f_lo; od[dn][1] *= f_lo;
            od[dn][2] *= f_hi; od[dn][3] *= f_hi;
        }
        uint32_t ph[2][4], pl[2][4];
#pragma unroll
        for (int ks = 0; ks < 2; ks++) {
            pack2(e[2*ks][0],   e[2*ks][1],   ph[ks][0], pl[ks][0]);
            pack2(e[2*ks][2],   e[2*ks][3],   ph[ks][1], pl[ks][1]);
            pack2(e[2*ks+1][0], e[2*ks+1][1], ph[ks][2], pl[ks][2]);
            pack2(e[2*ks+1][2], e[2*ks+1][3], ph[ks][3], pl[ks][3]);
        }
#pragma unroll
        for (int ks = 0; ks < 2; ks++) {
#pragma unroll
            for (int dn = 0; dn < 2; dn++) {
                int vrow = dn * 8 + g;
                int kk = wn * 32 + ks * 16;
                uint32_t vb0 = *(uint32_t*)&VH[vrow * VP + kk + 2*tg];
                uint32_t vb1 = *(uint32_t*)&VH[vrow * VP + kk + 2*tg + 8];
                uint32_t vc0 = *(uint32_t*)&VL[vrow * VP + kk + 2*tg];
                uint32_t vc1 = *(uint32_t*)&VL[vrow * VP + kk + 2*tg + 8];
                mma16816(od[dn], ph[ks][0], ph[ks][1], ph[ks][2], ph[ks][3], vb0, vb1);
                mma16816(od[dn], pl[ks][0], pl[ks][1], pl[ks][2], pl[ks][3], vb0, vb1);
                mma16816(od[dn], ph[ks][0], ph[ks][1], ph[ks][2], ph[ks][3], vc0, vc1);
            }
        }
    }

#pragma unroll
    for (int dn = 0; dn < 2; dn++) {
        Of[wn][wm][g][dn*8 + 2*tg]       = od[dn][0];
        Of[wn][wm][g][dn*8 + 2*tg + 1]   = od[dn][1];
        Of[wn][wm][g+8][dn*8 + 2*tg]     = od[dn][2];
        Of[wn][wm][g+8][dn*8 + 2*tg + 1] = od[dn][3];
    }
    if (tg == 0 && wn == 0) {
        rsinv[rlo] = 1.f / rs_lo;
        rsinv[rhi] = 1.f / rs_hi;
    }
    __syncthreads();

    int q = tid & 31, dd = tid >> 5;
    float inv = rsinv[q];
    int qm = q >> 4, qr = q & 15;
    float* Ob = O + (long)b * 256 * 1024;
#pragma unroll
    for (int h2 = 0; h2 < 2; h2++) {
        int D = dd + h2 * 8;
        float v = (Of[0][qm][qr][D] + Of[1][qm][qr][D] +
                   Of[2][qm][qr][D] + Of[3][qm][qr][D]) * inv;
        Ob[(head * 64 + D * 4 + t) * 1024 + r0 + q] = v;
    }
}

// ---------------------------------------------------------------------------
// PE conv + residual; emits bf16 hi/lo split planes (exact R10: 1 px/thread)
// ---------------------------------------------------------------------------
__global__ void pe_kernel(const float* __restrict__ I, const float* __restrict__ pw,
                          const float* __restrict__ pb,
                          __nv_bfloat16* __restrict__ H, __nv_bfloat16* __restrict__ L,
                          long bsP) {
    int idx = blockIdx.x * 256 + threadIdx.x;
    if (idx >= 4 * 256 * 1024) return;
    int p = idx & 1023;
    int m = (idx >> 10) & 255;
    int b = idx >> 18;
    int h = p >> 5, w = p & 31;
    int co = m >> 2, t = m & 3, g = co >> 2;
    const float* Ib = I + (long)b * 256 * 1024;
    float acc = Ib[m * 1024 + p] + pb[m];
#pragma unroll
    for (int s = 0; s < 4; s++) {
        float sg = c_sgn[t * 4 + s];
        const float* wc = pw + ((long)c_cmp[t * 4 + s] * 64 + co) * 36;
#pragma unroll
        for (int cil = 0; cil < 4; cil++) {
            const float* in = Ib + ((g * 4 + cil) * 4 + s) * 1024;
            const float* wk = wc + cil * 9;
            float part = 0.f;
#pragma unroll
            for (int kh = 0; kh < 3; kh++) {
                int hh = h + kh - 1;
                if (hh < 0 || hh > 31) continue;
#pragma unroll
                for (int kw = 0; kw < 3; kw++) {
                    int ww = w + kw - 1;
                    if (ww < 0 || ww > 31) continue;
                    part += in[hh * 32 + ww] * wk[kh * 3 + kw];
                }
            }
            acc += sg * part;
        }
    }
    __nv_bfloat16 hh, ll;
    splitf(acc, hh, ll);
    long o = (long)b * bsP + (long)m * 1024 + p;
    H[o] = hh;
    L[o] = ll;
}

// ---------------------------------------------------------------------------
extern "C" void kernel_launch(void* const* d_in, const int* in_sizes, int n_in,
                              void* d_out, int out_size) {
    const float* x      = (const float*)d_in[0];
    const float* cv1_w  = (const float*)d_in[1];
    const float* bn1_g  = (const float*)d_in[2];
    const float* bn1_b  = (const float*)d_in[3];
    const float* qkv_w  = (const float*)d_in[4];
    const float* qkv_b  = (const float*)d_in[5];
    const float* proj_w = (const float*)d_in[6];
    const float* proj_b = (const float*)d_in[7];
    const float* pe_w   = (const float*)d_in[8];
    const float* pe_b   = (const float*)d_in[9];
    const float* ang    = (const float*)d_in[10];
    const float* anb    = (const float*)d_in[11];
    const float* f1w    = (const float*)d_in[12];
    const float* f1g    = (const float*)d_in[13];
    const float* f1b    = (const float*)d_in[14];
    const float* f2w    = (const float*)d_in[15];
    const float* f2g    = (const float*)d_in[16];
    const float* f2b    = (const float*)d_in[17];
    const float* cv2_w  = (const float*)d_in[18];
    const float* bn2_g  = (const float*)d_in[19];
    const float* bn2_b  = (const float*)d_in[20];

    float *buf1, *buf2, *buf3;
    __nv_bfloat16 *xh0, *xl0, *xh1, *xl1, *Wh, *Wl;
    cudaGetSymbolAddress((void**)&buf1, g_buf1);
    cudaGetSymbolAddress((void**)&buf2, g_buf2);
    cudaGetSymbolAddress((void**)&buf3, g_buf3);
    cudaGetSymbolAddress((void**)&xh0,  g_xh0);
    cudaGetSymbolAddress((void**)&xl0,  g_xl0);
    cudaGetSymbolAddress((void**)&xh1,  g_xh1);
    cudaGetSymbolAddress((void**)&xl1,  g_xl1);
    cudaGetSymbolAddress((void**)&Wh,   g_Wh);
    cudaGetSymbolAddress((void**)&Wl,   g_Wl);

    const long S512 = 512L * 1024, S768 = 768L * 1024, S256 = 256L * 1024;

    cudaFuncSetAttribute(mma_gemm_kernel,
                         cudaFuncAttributeMaxDynamicSharedMemorySize, GEMM_SMEM);

    expand_all_kernel<<<dim3(32, 6), 256>>>(cv1_w, qkv_w, proj_w, f1w, f2w, cv2_w, Wh, Wl);
    split_x_kernel<<<2048, 256>>>(x, xh0, xl0);

    // cv1 + iqbn(+relu) -> P1 (512 rows)
    mma_gemm_kernel<<<dim3(8, 8, 4), 128, GEMM_SMEM>>>(Wh + OFF_W1, Wl + OFF_W1, xh0, xl0,
                                                        buf1, nullptr, 512, 512, S512, S512);
    bn_fused_split<<<512, 256>>>(buf1, xh1, xl1, bn1_g, bn1_b, S512, S512, 1);

    // qkv
    mma_gemm_kernel<<<dim3(8, 12, 4), 128, GEMM_SMEM>>>(Wh + OFF_WQ, Wl + OFF_WQ, xh1, xl1,
                                                         buf2, qkv_b, 768, 256, S512, S768);

    // attention (tensor cores)
    attn_kernel<<<dim3(32, 16, 4), 256>>>(buf2, buf3);

    // pe conv + residual -> P0
    pe_kernel<<<4096, 256>>>(buf3, pe_w, pe_b, xh0, xl0, S512);

    // proj + attn_norm -> P0
    mma_gemm_kernel<<<dim3(8, 4, 4), 128, GEMM_SMEM>>>(Wh + OFF_WP, Wl + OFF_WP, xh0, xl0,
                                                        buf3, proj_b, 256, 256, S512, S256);
    bn_fused_split<<<256, 256>>>(buf3, xh0, xl0, ang, anb, S256, S512, 0);

    // ffn1 + bn(+relu) -> P0
    mma_gemm_kernel<<<dim3(8, 8, 4), 128, GEMM_SMEM>>>(Wh + OFF_F1, Wl + OFF_F1, xh0, xl0,
                                                        buf2, nullptr, 512, 256, S512, S512);
    bn_fused_split<<<512, 256>>>(buf2, xh0, xl0, f1g, f1b, S512, S512, 1);

    // ffn2 + bn -> P1 rows 0..255 (rows 256..511 = b from bn1)
    mma_gemm_kernel<<<dim3(8, 4, 4), 128, GEMM_SMEM>>>(Wh + OFF_F2, Wl + OFF_F2, xh0, xl0,
                                                        buf3, nullptr, 256, 512, S512, S256);
    bn_fused_split<<<256, 256>>>(buf3, xh1, xl1, f2g, f2b, S256, S512, 0);

    // cv2 on concat + bn + relu -> d_out
    mma_gemm_kernel<<<dim3(8, 8, 4), 128, GEMM_SMEM>>>(Wh + OFF_C2, Wl + OFF_C2, xh1, xl1,
                                                        buf2, nullptr, 512, 512, S512, S512);
    bn_fused_out<<<512, 256>>>(buf2, (float*)d_out, bn2_g, bn2_b, S512, S512, 1);
}

// round 14
// speedup vs baseline: 1.9630x; 1.0204x over previous
#include <cuda_runtime.h>
#include <cuda_bf16.h>
#include <cstdint>

// ---------------------------------------------------------------------------
// Quaternion Hamilton-product tables
// ---------------------------------------------------------------------------
__constant__ int   c_cmp[16] = {0,1,2,3,  1,0,3,2,  2,3,0,1,  3,2,1,0};
__constant__ float c_sgn[16] = {1.f,-1.f,-1.f,-1.f,
                                1.f, 1.f, 1.f,-1.f,
                                1.f,-1.f, 1.f, 1.f,
                                1.f, 1.f,-1.f, 1.f};

// ---------------------------------------------------------------------------
// Scratch (device globals)
// ---------------------------------------------------------------------------
__device__ float g_buf1[4*512*1024];
__device__ float g_buf2[4*768*1024];
__device__ float g_buf3[4*256*1024];
__device__ __align__(16) __nv_bfloat16 g_xh0[4*512*1024];
__device__ __align__(16) __nv_bfloat16 g_xl0[4*512*1024];
__device__ __align__(16) __nv_bfloat16 g_xh1[4*512*1024];
__device__ __align__(16) __nv_bfloat16 g_xl1[4*512*1024];
__device__ __align__(16) __nv_bfloat16 g_Wh[1048576];
__device__ __align__(16) __nv_bfloat16 g_Wl[1048576];

#define OFF_W1 0
#define OFF_WQ (OFF_W1 + 512*512)
#define OFF_WP (OFF_WQ + 768*256)
#define OFF_F1 (OFF_WP + 256*256)
#define OFF_F2 (OFF_F1 + 512*256)
#define OFF_C2 (OFF_F2 + 256*512)

__device__ __forceinline__ void splitf(float v, __nv_bfloat16& h, __nv_bfloat16& l) {
    h = __float2bfloat16(v);
    l = __float2bfloat16(v - __bfloat162float(h));
}

// Fast paired split via cvt.rn.bf16x2 — bit-identical to two splitf calls.
// Returns h = bf16(x) | bf16(y)<<16 ; l = bf16lo(x) | bf16lo(y)<<16
__device__ __forceinline__ uint32_t cvt2(float hi, float lo) {
    uint32_t d;
    asm("cvt.rn.bf16x2.f32 %0, %1, %2;" : "=r"(d) : "f"(hi), "f"(lo));
    return d;   // upper 16 = bf16(hi), lower 16 = bf16(lo)
}
__device__ __forceinline__ void pack2(float x, float y, uint32_t& h, uint32_t& l) {
    h = cvt2(y, x);
    float hx = __uint_as_float(h << 16);          // exact bf16(x) as f32
    float hy = __uint_as_float(h & 0xFFFF0000u);  // exact bf16(y) as f32
    l = cvt2(y - hy, x - hx);
}

// ---------------------------------------------------------------------------
// Fused expansion: quaternion weights -> dense bf16 hi/lo GEMM weights
// ---------------------------------------------------------------------------
__global__ void expand_all_kernel(const float* __restrict__ w0, const float* __restrict__ w1,
                                  const float* __restrict__ w2, const float* __restrict__ w3,
                                  const float* __restrict__ w4, const float* __restrict__ w5,
                                  __nv_bfloat16* __restrict__ Wh, __nv_bfloat16* __restrict__ Wl) {
    const int Couts[6] = {128,192,64,128,64,128};
    const int Cins [6] = {128, 64,64, 64,128,128};
    const int offs [6] = {OFF_W1,OFF_WQ,OFF_WP,OFF_F1,OFF_F2,OFF_C2};
    const float* srcs[6] = {w0,w1,w2,w3,w4,w5};
    int q = blockIdx.y;
    int Cout = Couts[q], Cin = Cins[q];
    const float* w = srcs[q];
    int off = offs[q];
    int total = 16 * Cout * Cin;
    for (int i = blockIdx.x * blockDim.x + threadIdx.x; i < total;
         i += gridDim.x * blockDim.x) {
        int s = i & 3, t = (i >> 2) & 3;
        int rest = i >> 4;
        int ci = rest % Cin, co = rest / Cin;
        float val = c_sgn[t*4 + s] * w[c_cmp[t*4 + s] * Cout * Cin + co * Cin + ci];
        __nv_bfloat16 h, l;
        splitf(val, h, l);
        int idx = off + (co*4 + t) * (4*Cin) + ci*4 + s;
        Wh[idx] = h;
        Wl[idx] = l;
    }
}

// ---------------------------------------------------------------------------
// Plain fp32 -> bf16 hi/lo split (network input x) — paired cvt
// ---------------------------------------------------------------------------
__global__ __launch_bounds__(256) void split_x_kernel(const float* __restrict__ X,
                                                      __nv_bfloat16* __restrict__ H,
                                                      __nv_bfloat16* __restrict__ L) {
    int i = blockIdx.x * 256 + threadIdx.x;
    float4 v = ((const float4*)X)[i];
    uint32_t h01, l01, h23, l23;
    pack2(v.x, v.y, h01, l01);
    pack2(v.z, v.w, h23, l23);
    *(uint2*)(H + (long)i * 4) = make_uint2(h01, h23);
    *(uint2*)(L + (long)i * 4) = make_uint2(l01, l23);
}

// ---------------------------------------------------------------------------
// mma / ldmatrix helpers
// ---------------------------------------------------------------------------
__device__ __forceinline__ void mma16816(float* d, uint32_t a0, uint32_t a1,
                                         uint32_t a2, uint32_t a3,
                                         uint32_t b0, uint32_t b1) {
    asm volatile(
        "mma.sync.aligned.m16n8k16.row.col.f32.bf16.bf16.f32 "
        "{%0,%1,%2,%3}, {%4,%5,%6,%7}, {%8,%9}, {%0,%1,%2,%3};"
        : "+f"(d[0]), "+f"(d[1]), "+f"(d[2]), "+f"(d[3])
        : "r"(a0), "r"(a1), "r"(a2), "r"(a3), "r"(b0), "r"(b1));
}
__device__ __forceinline__ void ldsm4(uint32_t& r0, uint32_t& r1, uint32_t& r2,
                                      uint32_t& r3, uint32_t addr) {
    asm volatile("ldmatrix.sync.aligned.m8n8.x4.shared.b16 {%0,%1,%2,%3}, [%4];"
                 : "=r"(r0), "=r"(r1), "=r"(r2), "=r"(r3) : "r"(addr));
}
__device__ __forceinline__ void ldsm4t(uint32_t& r0, uint32_t& r1, uint32_t& r2,
                                       uint32_t& r3, uint32_t addr) {
    asm volatile("ldmatrix.sync.aligned.m8n8.x4.trans.shared.b16 {%0,%1,%2,%3}, [%4];"
                 : "=r"(r0), "=r"(r1), "=r"(r2), "=r"(r3) : "r"(addr));
}

// ---------------------------------------------------------------------------
// HMMA bf16-split GEMM (exact R10/R13 — untouched)
// ---------------------------------------------------------------------------
#define APITCH 40
#define BPITCH 136
#define A_PLANE (64*APITCH)
#define B_PLANE (32*BPITCH)
#define GBUF (2*A_PLANE + 2*B_PLANE)
#define GEMM_SMEM (2*GBUF*2)

__global__ __launch_bounds__(128) void mma_gemm_kernel(
    const __nv_bfloat16* __restrict__ Wh, const __nv_bfloat16* __restrict__ Wl,
    const __nv_bfloat16* __restrict__ Xh, const __nv_bfloat16* __restrict__ Xl,
    float* __restrict__ Y, const float* __restrict__ bias,
    int M, int K, long sX, long sY)
{
    extern __shared__ __nv_bfloat16 smd[];
    const uint32_t smem_base = (uint32_t)__cvta_generic_to_shared(smd);

    const int tid = threadIdx.x;
    const int wid = tid >> 5, lane = tid & 31;
    const int wm = wid & 1, wn = wid >> 1;
    const int g = lane >> 2, tg = lane & 3;
    const int mo = blockIdx.y * 64, no = blockIdx.x * 128;
    const __nv_bfloat16* Xhb = Xh + blockIdx.z * sX;
    const __nv_bfloat16* Xlb = Xl + blockIdx.z * sX;
    float* Yb = Y + blockIdx.z * sY;

    const int am = tid >> 1, ak = (tid & 1) * 16;
    const int bcol = (tid & 31) * 4;
    const int bk0 = (tid >> 5) * 2;

    float acc[2][8][4] = {};
    const int nch = K >> 5;

    uint4 awh[2], awl[2];
    uint2 bh[4][2], bl[4][2];

#define LOAD_REGS(kt)                                                            \
    {                                                                            \
        const __nv_bfloat16* Ah = Wh + (long)(mo + am) * K + (kt) + ak;          \
        const __nv_bfloat16* Al = Wl + (long)(mo + am) * K + (kt) + ak;          \
        awh[0] = *(const uint4*)Ah; awh[1] = *(const uint4*)(Ah + 8);            \
        awl[0] = *(const uint4*)Al; awl[1] = *(const uint4*)(Al + 8);            \
        _Pragma("unroll")                                                        \
        for (int I = 0; I < 4; I++) {                                            \
            int kr = (kt) + bk0 + 8 * I;                                         \
            const __nv_bfloat16* Bh = Xhb + (long)kr * 1024 + no + bcol;         \
            const __nv_bfloat16* Bl = Xlb + (long)kr * 1024 + no + bcol;         \
            bh[I][0] = *(const uint2*)Bh; bh[I][1] = *(const uint2*)(Bh + 1024); \
            bl[I][0] = *(const uint2*)Bl; bl[I][1] = *(const uint2*)(Bl + 1024); \
        }                                                                        \
    }

#define STORE_SMEM(buf)                                                          \
    {                                                                            \
        __nv_bfloat16* base = smd + (buf) * GBUF;                                \
        uint32_t* dH = (uint32_t*)(base + am * APITCH + ak);                     \
        uint32_t* dL = (uint32_t*)(base + A_PLANE + am * APITCH + ak);           \
        *(uint4*)dH = awh[0]; *(uint4*)(dH + 4) = awh[1];                        \
        *(uint4*)dL = awl[0]; *(uint4*)(dL + 4) = awl[1];                        \
        __nv_bfloat16* BH = base + 2 * A_PLANE;                                  \
        __nv_bfloat16* BL = base + 2 * A_PLANE + B_PLANE;                        \
        _Pragma("unroll")                                                        \
        for (int I = 0; I < 4; I++) {                                            \
            int kr = bk0 + 8 * I;                                                \
            *(uint2*)(BH + kr * BPITCH + bcol)       = bh[I][0];                 \
            *(uint2*)(BH + (kr + 1) * BPITCH + bcol) = bh[I][1];                 \
            *(uint2*)(BL + kr * BPITCH + bcol)       = bl[I][0];                 \
            *(uint2*)(BL + (kr + 1) * BPITCH + bcol) = bl[I][1];                 \
        }                                                                        \
    }

    LOAD_REGS(0);
    STORE_SMEM(0);
    if (nch > 1) LOAD_REGS(32);
    __syncthreads();

    const int a_row_l = lane & 15;
    const int a_khalf = (lane >> 4) * 8;
    const int b_krow  = (lane & 7) + 8 * ((lane >> 3) & 1);
    const int b_nhalf = (lane >> 4) * 8;

    for (int ch = 0; ch < nch; ch++) {
        if (ch + 1 < nch) STORE_SMEM((ch + 1) & 1);
        if (ch + 2 < nch) LOAD_REGS((ch + 2) * 32);

        uint32_t bufu = (uint32_t)((ch & 1) * GBUF) * 2u;
        uint32_t AH = smem_base + bufu;
        uint32_t ALo = AH + A_PLANE * 2;
        uint32_t BH = AH + 4 * A_PLANE;
        uint32_t BLo = BH + B_PLANE * 2;

#pragma unroll
        for (int k0 = 0; k0 < 32; k0 += 16) {
            uint32_t ah[2][4], al[2][4];
#pragma unroll
            for (int mt = 0; mt < 2; mt++) {
                int rowb = wm * 32 + mt * 16;
                uint32_t off = (uint32_t)((rowb + a_row_l) * APITCH + k0 + a_khalf) * 2u;
                ldsm4(ah[mt][0], ah[mt][1], ah[mt][2], ah[mt][3], AH + off);
                ldsm4(al[mt][0], al[mt][1], al[mt][2], al[mt][3], ALo + off);
            }
#pragma unroll
            for (int ntp = 0; ntp < 4; ntp++) {
                int nbase = wn * 64 + ntp * 16;
                uint32_t off = (uint32_t)((k0 + b_krow) * BPITCH + nbase + b_nhalf) * 2u;
                uint32_t bh0, bh1, bh2, bh3, bl0, bl1, bl2, bl3;
                ldsm4t(bh0, bh1, bh2, bh3, BH + off);
                ldsm4t(bl0, bl1, bl2, bl3, BLo + off);
#pragma unroll
                for (int mt = 0; mt < 2; mt++) {
                    float* d0 = acc[mt][ntp * 2];
                    float* d1 = acc[mt][ntp * 2 + 1];
                    mma16816(d0, ah[mt][0], ah[mt][1], ah[mt][2], ah[mt][3], bh0, bh1);
                    mma16816(d0, al[mt][0], al[mt][1], al[mt][2], al[mt][3], bh0, bh1);
                    mma16816(d0, ah[mt][0], ah[mt][1], ah[mt][2], ah[mt][3], bl0, bl1);
                    mma16816(d1, ah[mt][0], ah[mt][1], ah[mt][2], ah[mt][3], bh2, bh3);
                    mma16816(d1, al[mt][0], al[mt][1], al[mt][2], al[mt][3], bh2, bh3);
                    mma16816(d1, ah[mt][0], ah[mt][1], ah[mt][2], ah[mt][3], bl2, bl3);
                }
            }
        }
        if (ch + 1 < nch) __syncthreads();
    }

#pragma unroll
    for (int mt = 0; mt < 2; mt++) {
        int r0 = mo + wm * 32 + mt * 16 + g;
        int r1 = r0 + 8;
        float bv0 = bias ? bias[r0] : 0.f;
        float bv1 = bias ? bias[r1] : 0.f;
#pragma unroll
        for (int nt = 0; nt < 8; nt++) {
            int c = no + wn * 64 + nt * 8 + 2 * tg;
            float* d = acc[mt][nt];
            *(float2*)(Yb + (long)r0 * 1024 + c) = make_float2(d[0] + bv0, d[1] + bv0);
            *(float2*)(Yb + (long)r1 * 1024 + c) = make_float2(d[2] + bv1, d[3] + bv1);
        }
    }
#undef LOAD_REGS
#undef STORE_SMEM
}

// ---------------------------------------------------------------------------
// Fused BN: stats + apply + bf16 split (paired cvt in epilogue)
// ---------------------------------------------------------------------------
__global__ __launch_bounds__(256) void bn_fused_split(
    const float* __restrict__ X, __nv_bfloat16* __restrict__ H,
    __nv_bfloat16* __restrict__ L,
    const float* __restrict__ g, const float* __restrict__ be,
    long bsX, long bsP, int relu)
{
    int m = blockIdx.x, tid = threadIdx.x;
    float4 v[4];
    float s = 0.f, sq = 0.f;
#pragma unroll
    for (int b = 0; b < 4; b++) {
        v[b] = *(const float4*)(X + b * bsX + (long)m * 1024 + tid * 4);
        s  += v[b].x + v[b].y + v[b].z + v[b].w;
        sq += v[b].x*v[b].x + v[b].y*v[b].y + v[b].z*v[b].z + v[b].w*v[b].w;
    }
#pragma unroll
    for (int o = 16; o; o >>= 1) {
        s  += __shfl_xor_sync(0xffffffffu, s, o);
        sq += __shfl_xor_sync(0xffffffffu, sq, o);
    }
    __shared__ float ps[8], pq[8], bsc[1], bsh[1];
    if ((tid & 31) == 0) { ps[tid >> 5] = s; pq[tid >> 5] = sq; }
    __syncthreads();
    if (tid == 0) {
        s = 0.f; sq = 0.f;
#pragma unroll
        for (int i = 0; i < 8; i++) { s += ps[i]; sq += pq[i]; }
        float mean = s * (1.f / 4096.f);
        float var  = sq * (1.f / 4096.f) - mean * mean;
        float rstd = rsqrtf(var + 1e-5f);
        float sc = g[m] * rstd;
        bsc[0] = sc;
        bsh[0] = be[m] - mean * sc;
    }
    __syncthreads();
    float sc = bsc[0], sh = bsh[0];
#pragma unroll
    for (int b = 0; b < 4; b++) {
        float4 w = v[b];
        w.x = w.x * sc + sh; w.y = w.y * sc + sh;
        w.z = w.z * sc + sh; w.w = w.w * sc + sh;
        if (relu) {
            w.x = fmaxf(w.x, 0.f); w.y = fmaxf(w.y, 0.f);
            w.z = fmaxf(w.z, 0.f); w.w = fmaxf(w.w, 0.f);
        }
        uint32_t h01, l01, h23, l23;
        pack2(w.x, w.y, h01, l01);
        pack2(w.z, w.w, h23, l23);
        long o = (long)b * bsP + (long)m * 1024 + tid * 4;
        *(uint2*)(H + o) = make_uint2(h01, h23);
        *(uint2*)(L + o) = make_uint2(l01, l23);
    }
}

__global__ __launch_bounds__(256) void bn_fused_out(
    const float* __restrict__ X, float* __restrict__ Y,
    const float* __restrict__ g, const float* __restrict__ be,
    long bsX, long bsY, int relu)
{
    int m = blockIdx.x, tid = threadIdx.x;
    float4 v[4];
    float s = 0.f, sq = 0.f;
#pragma unroll
    for (int b = 0; b < 4; b++) {
        v[b] = *(const float4*)(X + b * bsX + (long)m * 1024 + tid * 4);
        s  += v[b].x + v[b].y + v[b].z + v[b].w;
        sq += v[b].x*v[b].x + v[b].y*v[b].y + v[b].z*v[b].z + v[b].w*v[b].w;
    }
#pragma unroll
    for (int o = 16; o; o >>= 1) {
        s  += __shfl_xor_sync(0xffffffffu, s, o);
        sq += __shfl_xor_sync(0xffffffffu, sq, o);
    }
    __shared__ float ps[8], pq[8], bsc[1], bsh[1];
    if ((tid & 31) == 0) { ps[tid >> 5] = s; pq[tid >> 5] = sq; }
    __syncthreads();
    if (tid == 0) {
        s = 0.f; sq = 0.f;
#pragma unroll
        for (int i = 0; i < 8; i++) { s += ps[i]; sq += pq[i]; }
        float mean = s * (1.f / 4096.f);
        float var  = sq * (1.f / 4096.f) - mean * mean;
        float rstd = rsqrtf(var + 1e-5f);
        float sc = g[m] * rstd;
        bsc[0] = sc;
        bsh[0] = be[m] - mean * sc;
    }
    __syncthreads();
    float sc = bsc[0], sh = bsh[0];
#pragma unroll
    for (int b = 0; b < 4; b++) {
        float4 w = v[b];
        w.x = w.x * sc + sh; w.y = w.y * sc + sh;
        w.z = w.z * sc + sh; w.w = w.w * sc + sh;
        if (relu) {
            w.x = fmaxf(w.x, 0.f); w.y = fmaxf(w.y, 0.f);
            w.z = fmaxf(w.z, 0.f); w.w = fmaxf(w.w, 0.f);
        }
        *(float4*)(Y + (long)b * bsY + (long)m * 1024 + tid * 4) = w;
    }
}

// ---------------------------------------------------------------------------
// Tensor-core flash attention (R13 structure; pack2 now uses paired cvt)
// ---------------------------------------------------------------------------
#define QP 24
#define KP 24
#define VP 136

__global__ __launch_bounds__(256) void attn_kernel(const float* __restrict__ Yq,
                                                   float* __restrict__ O) {
    __shared__ __nv_bfloat16 QH[32*QP], QL[32*QP];
    __shared__ __nv_bfloat16 KH[128*KP], KL[128*KP];
    __shared__ __nv_bfloat16 VH[16*VP], VL[16*VP];
    __shared__ float redmax[4][32], redsum[4][32];
    __shared__ float Of[4][2][16][17];
    __shared__ float rsinv[32];

    int b = blockIdx.z, head = blockIdx.y >> 2, t = blockIdx.y & 3;
    int r0 = blockIdx.x * 32;
    const float* Yb = Yq + (long)b * 768 * 1024;
    int tid = threadIdx.x, lane = tid & 31, wid = tid >> 5;
    int wm = wid & 1, wn = wid >> 1;
    int g = lane >> 2, tg = lane & 3;

    for (int i = tid; i < 512; i += 256) {
        int dd = i >> 5, q = i & 31;
        float v = Yb[(head * 192 + dd * 4 + t) * 1024 + r0 + q];
        __nv_bfloat16 h, l; splitf(v, h, l);
        QH[q * QP + dd] = h;
        QL[q * QP + dd] = l;
    }
    __syncthreads();

    uint32_t qh[4], ql[4];
    {
        int r = wm * 16 + g;
        qh[0] = *(uint32_t*)&QH[r * QP + 2*tg];
        qh[1] = *(uint32_t*)&QH[(r + 8) * QP + 2*tg];
        qh[2] = *(uint32_t*)&QH[r * QP + 2*tg + 8];
        qh[3] = *(uint32_t*)&QH[(r + 8) * QP + 2*tg + 8];
        ql[0] = *(uint32_t*)&QL[r * QP + 2*tg];
        ql[1] = *(uint32_t*)&QL[(r + 8) * QP + 2*tg];
        ql[2] = *(uint32_t*)&QL[r * QP + 2*tg + 8];
        ql[3] = *(uint32_t*)&QL[(r + 8) * QP + 2*tg + 8];
    }

    float od[2][4] = {};
    float rm_lo = -1e30f, rm_hi = -1e30f, rs_lo = 0.f, rs_hi = 0.f;
    const float sc = 0.25f;
    const int rlo = wm * 16 + g, rhi = rlo + 8;

    for (int ch = 0; ch < 8; ch++) {
        __syncthreads();
        for (int i = tid; i < 2048; i += 256) {
            int dd = i >> 7, key = i & 127;
            float kval = Yb[(head * 192 + 64 + dd * 4 + t) * 1024 + ch * 128 + key];
            __nv_bfloat16 h, l; splitf(kval, h, l);
            KH[key * KP + dd] = h; KL[key * KP + dd] = l;
            float vval = Yb[(head * 192 + 128 + dd * 4 + t) * 1024 + ch * 128 + key];
            splitf(vval, h, l);
            VH[dd * VP + key] = h; VL[dd * VP + key] = l;
        }
        __syncthreads();

        float sacc[4][4] = {};
#pragma unroll
        for (int nt = 0; nt < 4; nt++) {
            int nb = wn * 32 + nt * 8 + g;
            uint32_t kb0 = *(uint32_t*)&KH[nb * KP + 2*tg];
            uint32_t kb1 = *(uint32_t*)&KH[nb * KP + 2*tg + 8];
            uint32_t kc0 = *(uint32_t*)&KL[nb * KP + 2*tg];
            uint32_t kc1 = *(uint32_t*)&KL[nb * KP + 2*tg + 8];
            mma16816(sacc[nt], qh[0], qh[1], qh[2], qh[3], kb0, kb1);
            mma16816(sacc[nt], ql[0], ql[1], ql[2], ql[3], kb0, kb1);
            mma16816(sacc[nt], qh[0], qh[1], qh[2], qh[3], kc0, kc1);
        }
        float mx_lo = -1e30f, mx_hi = -1e30f;
#pragma unroll
        for (int nt = 0; nt < 4; nt++) {
            sacc[nt][0] *= sc; sacc[nt][1] *= sc;
            sacc[nt][2] *= sc; sacc[nt][3] *= sc;
            mx_lo = fmaxf(mx_lo, fmaxf(sacc[nt][0], sacc[nt][1]));
            mx_hi = fmaxf(mx_hi, fmaxf(sacc[nt][2], sacc[nt][3]));
        }
        mx_lo = fmaxf(mx_lo, __shfl_xor_sync(0xffffffffu, mx_lo, 1));
        mx_lo = fmaxf(mx_lo, __shfl_xor_sync(0xffffffffu, mx_lo, 2));
        mx_hi = fmaxf(mx_hi, __shfl_xor_sync(0xffffffffu, mx_hi, 1));
        mx_hi = fmaxf(mx_hi, __shfl_xor_sync(0xffffffffu, mx_hi, 2));
        if (tg == 0) { redmax[wn][rlo] = mx_lo; redmax[wn][rhi] = mx_hi; }
        __syncthreads();

        float cm_lo = fmaxf(fmaxf(redmax[0][rlo], redmax[1][rlo]),
                            fmaxf(redmax[2][rlo], redmax[3][rlo]));
        float cm_hi = fmaxf(fmaxf(redmax[0][rhi], redmax[1][rhi]),
                            fmaxf(redmax[2][rhi], redmax[3][rhi]));
        float nm_lo = fmaxf(rm_lo, cm_lo), f_lo = __expf(rm_lo - nm_lo);
        float nm_hi = fmaxf(rm_hi, cm_hi), f_hi = __expf(rm_hi - nm_hi);
        rm_lo = nm_lo; rm_hi = nm_hi;

        float e[4][4];
        float sum_lo = 0.f, sum_hi = 0.f;
#pragma unroll
        for (int nt = 0; nt < 4; nt++) {
            e[nt][0] = __expf(sacc[nt][0] - nm_lo);
            e[nt][1] = __expf(sacc[nt][1] - nm_lo);
            e[nt][2] = __expf(sacc[nt][2] - nm_hi);
            e[nt][3] = __expf(sacc[nt][3] - nm_hi);
            sum_lo += e[nt][0] + e[nt][1];
            sum_hi += e[nt][2] + e[nt][3];
        }
        sum_lo += __shfl_xor_sync(0xffffffffu, sum_lo, 1);
        sum_lo += __shfl_xor_sync(0xffffffffu, sum_lo, 2);
        sum_hi += __shfl_xor_sync(0xffffffffu, sum_hi, 1);
        sum_hi += __shfl_xor_sync(0xffffffffu, sum_hi, 2);
        if (tg == 0) { redsum[wn][rlo] = sum_lo; redsum[wn][rhi] = sum_hi; }
        __syncthreads();

        rs_lo = rs_lo * f_lo + redsum[0][rlo] + redsum[1][rlo] + redsum[2][rlo] + redsum[3][rlo];
        rs_hi = rs_hi * f_hi + redsum[0][rhi] + redsum[1][rhi] + redsum[2][rhi] + redsum[3][rhi];

#pragma unroll
        for (int dn = 0; dn < 2; dn++) {
            od[dn][0] *= f_lo; od[dn][1] *= f_lo;
            od[dn][2] *= f_hi; od[dn][3] *= f_hi;
        }
        uint32_t ph[2][4], pl[2][4];
#pragma unroll
        for (int ks = 0; ks < 2; ks++) {
            pack2(e[2*ks][0],   e[2*ks][1],   ph[ks][0], pl[ks][0]);
            pack2(e[2*ks][2],   e[2*ks][3],   ph[ks][1], pl[ks][1]);
            pack2(e[2*ks+1][0], e[2*ks+1][1], ph[ks][2], pl[ks][2]);
            pack2(e[2*ks+1][2], e[2*ks+1][3], ph[ks][3], pl[ks][3]);
        }
#pragma unroll
        for (int ks = 0; ks < 2; ks++) {
#pragma unroll
            for (int dn = 0; dn < 2; dn++) {
                int vrow = dn * 8 + g;
                int kk = wn * 32 + ks * 16;
                uint32_t vb0 = *(uint32_t*)&VH[vrow * VP + kk + 2*tg];
                uint32_t vb1 = *(uint32_t*)&VH[vrow * VP + kk + 2*tg + 8];
                uint32_t vc0 = *(uint32_t*)&VL[vrow * VP + kk + 2*tg];
                uint32_t vc1 = *(uint32_t*)&VL[vrow * VP + kk + 2*tg + 8];
                mma16816(od[dn], ph[ks][0], ph[ks][1], ph[ks][2], ph[ks][3], vb0, vb1);
                mma16816(od[dn], pl[ks][0], pl[ks][1], pl[ks][2], pl[ks][3], vb0, vb1);
                mma16816(od[dn], ph[ks][0], ph[ks][1], ph[ks][2], ph[ks][3], vc0, vc1);
            }
        }
    }

#pragma unroll
    for (int dn = 0; dn < 2; dn++) {
        Of[wn][wm][g][dn*8 + 2*tg]       = od[dn][0];
        Of[wn][wm][g][dn*8 + 2*tg + 1]   = od[dn][1];
        Of[wn][wm][g+8][dn*8 + 2*tg]     = od[dn][2];
        Of[wn][wm][g+8][dn*8 + 2*tg + 1] = od[dn][3];
    }
    if (tg == 0 && wn == 0) {
        rsinv[rlo] = 1.f / rs_lo;
        rsinv[rhi] = 1.f / rs_hi;
    }
    __syncthreads();

    int q = tid & 31, dd = tid >> 5;
    float inv = rsinv[q];
    int qm = q >> 4, qr = q & 15;
    float* Ob = O + (long)b * 256 * 1024;
#pragma unroll
    for (int h2 = 0; h2 < 2; h2++) {
        int D = dd + h2 * 8;
        float v = (Of[0][qm][qr][D] + Of[1][qm][qr][D] +
                   Of[2][qm][qr][D] + Of[3][qm][qr][D]) * inv;
        Ob[(head * 64 + D * 4 + t) * 1024 + r0 + q] = v;
    }
}

// ---------------------------------------------------------------------------
// PE conv + residual; emits bf16 hi/lo split planes (exact R13: 1 px/thread)
// ---------------------------------------------------------------------------
__global__ void pe_kernel(const float* __restrict__ I, const float* __restrict__ pw,
                          const float* __restrict__ pb,
                          __nv_bfloat16* __restrict__ H, __nv_bfloat16* __restrict__ L,
                          long bsP) {
    int idx = blockIdx.x * 256 + threadIdx.x;
    if (idx >= 4 * 256 * 1024) return;
    int p = idx & 1023;
    int m = (idx >> 10) & 255;
    int b = idx >> 18;
    int h = p >> 5, w = p & 31;
    int co = m >> 2, t = m & 3, g = co >> 2;
    const float* Ib = I + (long)b * 256 * 1024;
    float acc = Ib[m * 1024 + p] + pb[m];
#pragma unroll
    for (int s = 0; s < 4; s++) {
        float sg = c_sgn[t * 4 + s];
        const float* wc = pw + ((long)c_cmp[t * 4 + s] * 64 + co) * 36;
#pragma unroll
        for (int cil = 0; cil < 4; cil++) {
            const float* in = Ib + ((g * 4 + cil) * 4 + s) * 1024;
            const float* wk = wc + cil * 9;
            float part = 0.f;
#pragma unroll
            for (int kh = 0; kh < 3; kh++) {
                int hh = h + kh - 1;
                if (hh < 0 || hh > 31) continue;
#pragma unroll
                for (int kw = 0; kw < 3; kw++) {
                    int ww = w + kw - 1;
                    if (ww < 0 || ww > 31) continue;
                    part += in[hh * 32 + ww] * wk[kh * 3 + kw];
                }
            }
            acc += sg * part;
        }
    }
    __nv_bfloat16 hh, ll;
    splitf(acc, hh, ll);
    long o = (long)b * bsP + (long)m * 1024 + p;
    H[o] = hh;
    L[o] = ll;
}

// ---------------------------------------------------------------------------
extern "C" void kernel_launch(void* const* d_in, const int* in_sizes, int n_in,
                              void* d_out, int out_size) {
    const float* x      = (const float*)d_in[0];
    const float* cv1_w  = (const float*)d_in[1];
    const float* bn1_g  = (const float*)d_in[2];
    const float* bn1_b  = (const float*)d_in[3];
    const float* qkv_w  = (const float*)d_in[4];
    const float* qkv_b  = (const float*)d_in[5];
    const float* proj_w = (const float*)d_in[6];
    const float* proj_b = (const float*)d_in[7];
    const float* pe_w   = (const float*)d_in[8];
    const float* pe_b   = (const float*)d_in[9];
    const float* ang    = (const float*)d_in[10];
    const float* anb    = (const float*)d_in[11];
    const float* f1w    = (const float*)d_in[12];
    const float* f1g    = (const float*)d_in[13];
    const float* f1b    = (const float*)d_in[14];
    const float* f2w    = (const float*)d_in[15];
    const float* f2g    = (const float*)d_in[16];
    const float* f2b    = (const float*)d_in[17];
    const float* cv2_w  = (const float*)d_in[18];
    const float* bn2_g  = (const float*)d_in[19];
    const float* bn2_b  = (const float*)d_in[20];

    float *buf1, *buf2, *buf3;
    __nv_bfloat16 *xh0, *xl0, *xh1, *xl1, *Wh, *Wl;
    cudaGetSymbolAddress((void**)&buf1, g_buf1);
    cudaGetSymbolAddress((void**)&buf2, g_buf2);
    cudaGetSymbolAddress((void**)&buf3, g_buf3);
    cudaGetSymbolAddress((void**)&xh0,  g_xh0);
    cudaGetSymbolAddress((void**)&xl0,  g_xl0);
    cudaGetSymbolAddress((void**)&xh1,  g_xh1);
    cudaGetSymbolAddress((void**)&xl1,  g_xl1);
    cudaGetSymbolAddress((void**)&Wh,   g_Wh);
    cudaGetSymbolAddress((void**)&Wl,   g_Wl);

    const long S512 = 512L * 1024, S768 = 768L * 1024, S256 = 256L * 1024;

    cudaFuncSetAttribute(mma_gemm_kernel,
                         cudaFuncAttributeMaxDynamicSharedMemorySize, GEMM_SMEM);

    expand_all_kernel<<<dim3(32, 6), 256>>>(cv1_w, qkv_w, proj_w, f1w, f2w, cv2_w, Wh, Wl);
    split_x_kernel<<<2048, 256>>>(x, xh0, xl0);

    // cv1 + iqbn(+relu) -> P1 (512 rows)
    mma_gemm_kernel<<<dim3(8, 8, 4), 128, GEMM_SMEM>>>(Wh + OFF_W1, Wl + OFF_W1, xh0, xl0,
                                                        buf1, nullptr, 512, 512, S512, S512);
    bn_fused_split<<<512, 256>>>(buf1, xh1, xl1, bn1_g, bn1_b, S512, S512, 1);

    // qkv
    mma_gemm_kernel<<<dim3(8, 12, 4), 128, GEMM_SMEM>>>(Wh + OFF_WQ, Wl + OFF_WQ, xh1, xl1,
                                                         buf2, qkv_b, 768, 256, S512, S768);

    // attention (tensor cores)
    attn_kernel<<<dim3(32, 16, 4), 256>>>(buf2, buf3);

    // pe conv + residual -> P0
    pe_kernel<<<4096, 256>>>(buf3, pe_w, pe_b, xh0, xl0, S512);

    // proj + attn_norm -> P0
    mma_gemm_kernel<<<dim3(8, 4, 4), 128, GEMM_SMEM>>>(Wh + OFF_WP, Wl + OFF_WP, xh0, xl0,
                                                        buf3, proj_b, 256, 256, S512, S256);
    bn_fused_split<<<256, 256>>>(buf3, xh0, xl0, ang, anb, S256, S512, 0);

    // ffn1 + bn(+relu) -> P0
    mma_gemm_kernel<<<dim3(8, 8, 4), 128, GEMM_SMEM>>>(Wh + OFF_F1, Wl + OFF_F1, xh0, xl0,
                                                        buf2, nullptr, 512, 256, S512, S512);
    bn_fused_split<<<512, 256>>>(buf2, xh0, xl0, f1g, f1b, S512, S512, 1);

    // ffn2 + bn -> P1 rows 0..255 (rows 256..511 = b from bn1)
    mma_gemm_kernel<<<dim3(8, 4, 4), 128, GEMM_SMEM>>>(Wh + OFF_F2, Wl + OFF_F2, xh0, xl0,
                                                        buf3, nullptr, 256, 512, S512, S256);
    bn_fused_split<<<256, 256>>>(buf3, xh1, xl1, f2g, f2b, S256, S512, 0);

    // cv2 on concat + bn + relu -> d_out
    mma_gemm_kernel<<<dim3(8, 8, 4), 128, GEMM_SMEM>>>(Wh + OFF_C2, Wl + OFF_C2, xh1, xl1,
                                                        buf2, nullptr, 512, 512, S512, S512);
    bn_fused_out<<<512, 256>>>(buf2, (float*)d_out, bn2_g, bn2_b, S512, S512, 1);
}